// round 2
// baseline (speedup 1.0000x reference)
#include <cuda_runtime.h>
#include <math.h>

// Problem constants (fixed by the dataset)
constexpr int B_  = 2;
constexpr int N_  = 2048;
constexpr int C_  = 384;
constexpr int NH_ = 12;
constexpr int HD_ = 32;
constexpr int M_  = B_ * N_;     // 4096 tokens
constexpr int C2_ = 2 * C_;      // 768

// ---------------- scratch (device globals; no allocation allowed) ----------
__device__ float g_qtmp[M_ * C_];        // x @ q_w.T + q_b        (B,N,C)
__device__ float g_kvtmp[M_ * C2_];      // x @ kv_w.T + kv_b      (B,N,2C)
__device__ float g_q[B_ * NH_ * N_ * HD_];   // normalized+embedded+scaled Q, [bh][n][d]
__device__ float g_k[B_ * NH_ * N_ * HD_];   // normalized K,               [bh][n][d]
__device__ float g_v[B_ * NH_ * N_ * HD_];   // V,                          [bh][n][d]
__device__ float g_att[M_ * C_];         // attention output in (B,N,C)

// ---------------------------------------------------------------------------
// GEMM: out[m][j] = sum_k X[m][k] * W[j][k] + bias[j]
// X: [4096, 384] row-major, W: [Nout, 384] row-major.
// 64x64 block tile, BK=16, 256 threads, 4x4 register tile.
// ---------------------------------------------------------------------------
__global__ void gemm_xwT_kernel(const float* __restrict__ X,
                                const float* __restrict__ W,
                                const float* __restrict__ bias,
                                float* __restrict__ out, int Nout) {
    constexpr int K = C_;
    __shared__ float As[16][68];
    __shared__ float Bs[16][68];
    const int bm = blockIdx.y * 64;
    const int bn = blockIdx.x * 64;
    const int t  = threadIdx.x;           // 0..255
    const int tx = t & 15;                // col group
    const int ty = t >> 4;                // row group

    float acc[4][4];
#pragma unroll
    for (int i = 0; i < 4; i++)
#pragma unroll
        for (int j = 0; j < 4; j++) acc[i][j] = 0.f;

    for (int k0 = 0; k0 < K; k0 += 16) {
#pragma unroll
        for (int i = 0; i < 4; i++) {
            int idx = t + i * 256;        // 0..1023
            int m   = idx >> 4;
            int kk  = idx & 15;
            As[kk][m] = X[(size_t)(bm + m) * K + k0 + kk];
            Bs[kk][m] = W[(size_t)(bn + m) * K + k0 + kk];
        }
        __syncthreads();
#pragma unroll
        for (int kk = 0; kk < 16; kk++) {
            float a[4], b[4];
#pragma unroll
            for (int i = 0; i < 4; i++) a[i] = As[kk][ty * 4 + i];
#pragma unroll
            for (int j = 0; j < 4; j++) b[j] = Bs[kk][tx * 4 + j];
#pragma unroll
            for (int i = 0; i < 4; i++)
#pragma unroll
                for (int j = 0; j < 4; j++) acc[i][j] += a[i] * b[j];
        }
        __syncthreads();
    }
#pragma unroll
    for (int i = 0; i < 4; i++) {
        int m = bm + ty * 4 + i;
#pragma unroll
        for (int j = 0; j < 4; j++) {
            int n = bn + tx * 4 + j;
            out[(size_t)m * Nout + n] = acc[i][j] + bias[n];
        }
    }
}

// ---------------------------------------------------------------------------
// Epilogue: per (b,n,h) warp. L2-norm Q, add query embedding, scale by
// softplus(temperature)*log(N); L2-norm K; relayout Q/K/V to [bh][n][d].
// ---------------------------------------------------------------------------
__global__ void qkv_epilogue_kernel(const float* __restrict__ temperature,
                                    const float* __restrict__ qe) {
    const int warp = blockIdx.x * (blockDim.x >> 5) + (threadIdx.x >> 5);
    const int lane = threadIdx.x & 31;
    if (warp >= B_ * N_ * NH_) return;
    const int h  = warp % NH_;
    const int bn = warp / NH_;           // b*N + n
    const int n  = bn % N_;
    const int b  = bn / N_;

    const unsigned FULL = 0xFFFFFFFFu;

    // ---- Q ----
    float qv = g_qtmp[(size_t)bn * C_ + h * HD_ + lane];
    float ss = qv * qv;
#pragma unroll
    for (int o = 16; o; o >>= 1) ss += __shfl_xor_sync(FULL, ss, o);
    float denom = fmaxf(sqrtf(ss), 1e-12f);
    float scale = log1pf(expf(temperature[h])) * logf((float)N_);
    float qn = (qv / denom + qe[h * HD_ + lane]) * scale;
    size_t hi = ((size_t)(b * NH_ + h) * N_ + n) * HD_ + lane;
    g_q[hi] = qn;

    // ---- K ----
    float kv = g_kvtmp[(size_t)bn * C2_ + h * HD_ + lane];
    float ss2 = kv * kv;
#pragma unroll
    for (int o = 16; o; o >>= 1) ss2 += __shfl_xor_sync(FULL, ss2, o);
    g_k[hi] = kv / fmaxf(sqrtf(ss2), 1e-12f);

    // ---- V ----
    g_v[hi] = g_kvtmp[(size_t)bn * C2_ + C_ + h * HD_ + lane];
}

// ---------------------------------------------------------------------------
// Attention: per CTA = 32 q rows of one (b,h). Stream over 64-key tiles with
// online softmax. 256 threads.
// S-GEMM: thread (sy,sx) computes rows sy*4..+3 x keys {sx, sx+32}.
// O-GEMM: thread owns (row = t>>3, dims (t&7)*4 .. +3).
// ---------------------------------------------------------------------------
constexpr int BQ  = 32;
constexpr int BKT = 64;

__global__ void attn_kernel(const float* __restrict__ pos_bias) {
    __shared__ __align__(16) float qs[BQ][HD_ + 1];
    __shared__ __align__(16) float Ks[BKT][HD_ + 1];
    __shared__ __align__(16) float Vs[BKT][HD_];
    __shared__ __align__(16) float Ss[BQ][BKT + 1];
    __shared__ float pb[BKT];
    __shared__ float m_s[BQ], l_s[BQ], alpha_s[BQ];

    const int bh    = blockIdx.y;            // b*NH + h
    const int h     = bh % NH_;
    const int b     = bh / NH_;
    const int qbase = blockIdx.x * BQ;
    const int t     = threadIdx.x;           // 0..255
    const unsigned FULL = 0xFFFFFFFFu;

    const float* Qp = g_q + (size_t)bh * N_ * HD_;
    const float* Kp = g_k + (size_t)bh * N_ * HD_;
    const float* Vp = g_v + (size_t)bh * N_ * HD_;

    // load q tile
    for (int i = t; i < BQ * HD_; i += 256) {
        int r = i >> 5, d = i & 31;
        qs[r][d] = Qp[(size_t)(qbase + r) * HD_ + d];
    }
    if (t < BQ) { m_s[t] = -1e30f; l_s[t] = 0.f; }

    const int sx = t & 31;                   // key lane
    const int sy = t >> 5;                   // 8 groups of 4 rows
    const int orow = t >> 3;                 // O-GEMM row
    const int od   = (t & 7) * 4;            // O-GEMM 4-dim group
    float oacc[4] = {0.f, 0.f, 0.f, 0.f};

    __syncthreads();

    for (int kt = 0; kt < N_; kt += BKT) {
        // ---- load K, V, pos_bias tile ----
        for (int i = t; i < BKT * HD_; i += 256) {
            int r = i >> 5, d = i & 31;
            Ks[r][d] = Kp[(size_t)(kt + r) * HD_ + d];
            Vs[r][d] = Vp[(size_t)(kt + r) * HD_ + d];
        }
        if (t < BKT) pb[t] = pos_bias[(size_t)h * N_ + kt + t];
        __syncthreads();

        // ---- S = q . k^T + pos_bias ----
        {
            float s00 = 0, s01 = 0, s10 = 0, s11 = 0, s20 = 0, s21 = 0, s30 = 0, s31 = 0;
#pragma unroll
            for (int d = 0; d < HD_; d++) {
                float a0 = qs[sy * 4 + 0][d];
                float a1 = qs[sy * 4 + 1][d];
                float a2 = qs[sy * 4 + 2][d];
                float a3 = qs[sy * 4 + 3][d];
                float b0 = Ks[sx][d];
                float b1 = Ks[sx + 32][d];
                s00 += a0 * b0; s01 += a0 * b1;
                s10 += a1 * b0; s11 += a1 * b1;
                s20 += a2 * b0; s21 += a2 * b1;
                s30 += a3 * b0; s31 += a3 * b1;
            }
            float p0 = pb[sx], p1 = pb[sx + 32];
            Ss[sy * 4 + 0][sx] = s00 + p0; Ss[sy * 4 + 0][sx + 32] = s01 + p1;
            Ss[sy * 4 + 1][sx] = s10 + p0; Ss[sy * 4 + 1][sx + 32] = s11 + p1;
            Ss[sy * 4 + 2][sx] = s20 + p0; Ss[sy * 4 + 2][sx + 32] = s21 + p1;
            Ss[sy * 4 + 3][sx] = s30 + p0; Ss[sy * 4 + 3][sx + 32] = s31 + p1;
        }
        __syncthreads();

        // ---- online softmax: warp w handles rows 4w..4w+3 ----
        {
            int w = t >> 5, lane = t & 31;
#pragma unroll
            for (int i = 0; i < 4; i++) {
                int r = w * 4 + i;
                float v0 = Ss[r][lane], v1 = Ss[r][lane + 32];
                float mx = fmaxf(v0, v1);
#pragma unroll
                for (int o = 16; o; o >>= 1) mx = fmaxf(mx, __shfl_xor_sync(FULL, mx, o));
                float newm = fmaxf(m_s[r], mx);
                float e0 = __expf(v0 - newm);
                float e1 = __expf(v1 - newm);
                Ss[r][lane] = e0; Ss[r][lane + 32] = e1;
                float ls = e0 + e1;
#pragma unroll
                for (int o = 16; o; o >>= 1) ls += __shfl_xor_sync(FULL, ls, o);
                if (lane == 0) {
                    float al = __expf(m_s[r] - newm);
                    alpha_s[r] = al;
                    l_s[r] = l_s[r] * al + ls;
                    m_s[r] = newm;
                }
            }
        }
        __syncthreads();

        // ---- O += P @ V (with rescale) ----
        {
            float al = alpha_s[orow];
#pragma unroll
            for (int j = 0; j < 4; j++) oacc[j] *= al;
            const float4* vrow;
#pragma unroll 8
            for (int kk = 0; kk < BKT; kk++) {
                float p = Ss[orow][kk];
                vrow = reinterpret_cast<const float4*>(&Vs[kk][0]);
                float4 vv = vrow[od >> 2];
                oacc[0] += p * vv.x;
                oacc[1] += p * vv.y;
                oacc[2] += p * vv.z;
                oacc[3] += p * vv.w;
            }
        }
        __syncthreads();
    }

    // ---- finalize, write to (B,N,C) layout ----
    float inv = 1.f / l_s[orow];
    size_t obase = ((size_t)(b * N_ + qbase + orow)) * C_ + h * HD_ + od;
#pragma unroll
    for (int j = 0; j < 4; j++) g_att[obase + j] = oacc[j] * inv;
}

// ---------------------------------------------------------------------------
extern "C" void kernel_launch(void* const* d_in, const int* in_sizes, int n_in,
                              void* d_out, int out_size) {
    const float* x       = (const float*)d_in[0];
    const float* q_w     = (const float*)d_in[1];
    const float* q_b     = (const float*)d_in[2];
    const float* kv_w    = (const float*)d_in[3];
    const float* kv_b    = (const float*)d_in[4];
    const float* qe      = (const float*)d_in[5];
    const float* temp    = (const float*)d_in[6];
    const float* pos_b   = (const float*)d_in[7];
    const float* proj_w  = (const float*)d_in[8];
    const float* proj_b  = (const float*)d_in[9];
    float* out = (float*)d_out;

    float *p_qtmp, *p_kvtmp, *p_att;
    cudaGetSymbolAddress((void**)&p_qtmp, g_qtmp);
    cudaGetSymbolAddress((void**)&p_kvtmp, g_kvtmp);
    cudaGetSymbolAddress((void**)&p_att, g_att);

    // 1) Q projection: [4096,384] x [384,384]^T
    gemm_xwT_kernel<<<dim3(C_ / 64, M_ / 64), 256>>>(x, q_w, q_b, p_qtmp, C_);
    // 2) KV projection: [4096,384] x [768,384]^T
    gemm_xwT_kernel<<<dim3(C2_ / 64, M_ / 64), 256>>>(x, kv_w, kv_b, p_kvtmp, C2_);
    // 3) normalize / embed / scale / relayout
    {
        int warps = B_ * N_ * NH_;
        int blocks = (warps + 7) / 8;
        qkv_epilogue_kernel<<<blocks, 256>>>(temp, qe);
    }
    // 4) attention
    attn_kernel<<<dim3(N_ / BQ, B_ * NH_), 256>>>(pos_b);
    // 5) output projection into d_out
    gemm_xwT_kernel<<<dim3(C_ / 64, M_ / 64), 256>>>(p_att, proj_w, proj_b, out, C_);
}

// round 3
// speedup vs baseline: 1.3877x; 1.3877x over previous
#include <cuda_runtime.h>
#include <math.h>

// Problem constants (fixed by the dataset)
constexpr int B_  = 2;
constexpr int N_  = 2048;
constexpr int C_  = 384;
constexpr int NH_ = 12;
constexpr int HD_ = 32;
constexpr int M_  = B_ * N_;     // 4096 tokens
constexpr int C2_ = 2 * C_;      // 768

// ---------------- scratch (device globals; no allocation allowed) ----------
__device__ float g_qtmp[M_ * C_];            // x @ q_w.T + q_b
__device__ float g_kvtmp[M_ * C2_];          // x @ kv_w.T + kv_b
__device__ float g_q[B_ * NH_ * N_ * HD_];   // final Q,  [bh][n][d]
__device__ float g_k[B_ * NH_ * N_ * HD_];   // unit K,   [bh][n][d]
__device__ float g_v[B_ * NH_ * N_ * HD_];   // V,        [bh][n][d]
__device__ float g_att[M_ * C_];             // attention out (B,N,C)
__device__ float g_qmax[B_ * NH_ * N_];      // ||q_row||2 (upper bound helper)
__device__ float g_pbmax[NH_];               // max over pos_bias row

// ---------------------------------------------------------------------------
// Projection GEMM: out[m][j] = sum_k X[m][k]*W[j][k] + b[j].  K = 384.
// 128 threads, 64x64 tile, BK=64, 8x4 register tile, float4 k-vectorized.
// ---------------------------------------------------------------------------
__global__ __launch_bounds__(128) void gemm_xwT_v2(const float* __restrict__ X,
                                                   const float* __restrict__ W,
                                                   const float* __restrict__ bias,
                                                   float* __restrict__ out, int Nout) {
    __shared__ __align__(16) float Xs[64][68];
    __shared__ __align__(16) float Ws[64][68];
    const int bm = blockIdx.y * 64;
    const int bn = blockIdx.x * 64;
    const int t  = threadIdx.x;
    const int ty = t >> 4;          // 0..7  -> rows ty*8..+7
    const int tx = t & 15;          // 0..15 -> cols tx*4..+3

    float acc[8][4];
#pragma unroll
    for (int i = 0; i < 8; i++)
#pragma unroll
        for (int j = 0; j < 4; j++) acc[i][j] = 0.f;

    for (int k0 = 0; k0 < C_; k0 += 64) {
#pragma unroll
        for (int i = 0; i < 8; i++) {
            int id = t + i * 128;        // 0..1023
            int r  = id >> 4;            // 64 rows
            int kc = id & 15;            // 16 float4 per row
            *(float4*)&Xs[r][kc * 4] =
                ((const float4*)X)[((size_t)(bm + r) * C_ + k0) / 4 + kc];
            *(float4*)&Ws[r][kc * 4] =
                ((const float4*)W)[((size_t)(bn + r) * C_ + k0) / 4 + kc];
        }
        __syncthreads();
#pragma unroll
        for (int c = 0; c < 16; c++) {
            float4 b4[4];
#pragma unroll
            for (int j = 0; j < 4; j++) b4[j] = *(const float4*)&Ws[tx * 4 + j][c * 4];
#pragma unroll
            for (int i = 0; i < 8; i++) {
                float4 a = *(const float4*)&Xs[ty * 8 + i][c * 4];
#pragma unroll
                for (int j = 0; j < 4; j++)
                    acc[i][j] += a.x * b4[j].x + a.y * b4[j].y + a.z * b4[j].z + a.w * b4[j].w;
            }
        }
        __syncthreads();
    }
#pragma unroll
    for (int i = 0; i < 8; i++) {
        int m = bm + ty * 8 + i;
#pragma unroll
        for (int j = 0; j < 4; j++) {
            int n = bn + tx * 4 + j;
            out[(size_t)m * Nout + n] = acc[i][j] + bias[n];
        }
    }
}

// ---------------------------------------------------------------------------
// per-head max of pos_bias
// ---------------------------------------------------------------------------
__global__ void pbmax_kernel(const float* __restrict__ pb) {
    __shared__ float red[256];
    int h = blockIdx.x, t = threadIdx.x;
    float m = -1e30f;
    for (int i = t; i < N_; i += 256) m = fmaxf(m, pb[(size_t)h * N_ + i]);
    red[t] = m;
    __syncthreads();
    for (int s = 128; s; s >>= 1) {
        if (t < s) red[t] = fmaxf(red[t], red[t + s]);
        __syncthreads();
    }
    if (t == 0) g_pbmax[h] = red[0];
}

// ---------------------------------------------------------------------------
// Epilogue: per (b,n,h) warp. L2-norm Q, add embedding, scale; L2-norm K;
// relayout to [bh][n][d]; also store ||q_row|| for the softmax max bound.
// ---------------------------------------------------------------------------
__global__ void qkv_epilogue_kernel(const float* __restrict__ temperature,
                                    const float* __restrict__ qe) {
    const int warp = blockIdx.x * (blockDim.x >> 5) + (threadIdx.x >> 5);
    const int lane = threadIdx.x & 31;
    if (warp >= B_ * N_ * NH_) return;
    const int h  = warp % NH_;
    const int bn = warp / NH_;
    const int n  = bn % N_;
    const int b  = bn / N_;
    const unsigned FULL = 0xFFFFFFFFu;

    // ---- Q ----
    float qv = g_qtmp[(size_t)bn * C_ + h * HD_ + lane];
    float ss = qv * qv;
#pragma unroll
    for (int o = 16; o; o >>= 1) ss += __shfl_xor_sync(FULL, ss, o);
    float denom = fmaxf(sqrtf(ss), 1e-12f);
    float scale = log1pf(expf(temperature[h])) * logf((float)N_);
    float qn = (qv / denom + qe[h * HD_ + lane]) * scale;
    size_t hi = ((size_t)(b * NH_ + h) * N_ + n) * HD_ + lane;
    g_q[hi] = qn;

    // ||q_row||
    float ss3 = qn * qn;
#pragma unroll
    for (int o = 16; o; o >>= 1) ss3 += __shfl_xor_sync(FULL, ss3, o);
    if (lane == 0) g_qmax[(size_t)(b * NH_ + h) * N_ + n] = sqrtf(ss3);

    // ---- K ----
    float kv = g_kvtmp[(size_t)bn * C2_ + h * HD_ + lane];
    float ss2 = kv * kv;
#pragma unroll
    for (int o = 16; o; o >>= 1) ss2 += __shfl_xor_sync(FULL, ss2, o);
    g_k[hi] = kv / fmaxf(sqrtf(ss2), 1e-12f);

    // ---- V ----
    g_v[hi] = g_kvtmp[(size_t)bn * C2_ + C_ + h * HD_ + lane];
}

// ---------------------------------------------------------------------------
// Attention. CTA = 64 q rows of one (b,h), 128 threads, 64-key tiles.
// Fixed per-row softmax bound m = ||q_row|| + max(pos_bias[h]) -> no online
// rescaling, no max reductions; l accumulates in registers.
// S-GEMM : thread (ty,tx) -> rows ty*8..+7, cols tx*4..+3 (8x4)
// PV-GEMM: thread (ty,tx) -> rows ty*8..+7, dims tx*2..+1 (8x2)
// ---------------------------------------------------------------------------
__global__ __launch_bounds__(128) void attn_v2(const float* __restrict__ pos_bias) {
    __shared__ __align__(16) float qs[64][36];
    __shared__ __align__(16) float Ks[64][36];
    __shared__ __align__(16) float Vs[64][36];
    __shared__ __align__(16) float Ss[64][68];
    __shared__ float pb[64];

    const int bh    = blockIdx.y;
    const int h     = bh % NH_;
    const int b     = bh / NH_;
    const int qbase = blockIdx.x * 64;
    const int t     = threadIdx.x;
    const int ty    = t >> 4;
    const int tx    = t & 15;
    const unsigned FULL = 0xFFFFFFFFu;

    const float* Qp = g_q + (size_t)bh * N_ * HD_;
    const float* Kp = g_k + (size_t)bh * N_ * HD_;
    const float* Vp = g_v + (size_t)bh * N_ * HD_;

    // load q tile (64x32 floats = 512 float4, 4 per thread)
#pragma unroll
    for (int i = 0; i < 4; i++) {
        int id = t + i * 128;
        int r = id >> 3, d4 = id & 7;
        *(float4*)&qs[r][d4 * 4] = ((const float4*)Qp)[((size_t)(qbase + r) * HD_) / 4 + d4];
    }

    float mrow[8], lpart[8], oacc[8][2];
    const float pmax = g_pbmax[h];
#pragma unroll
    for (int i = 0; i < 8; i++) {
        mrow[i] = g_qmax[(size_t)bh * N_ + qbase + ty * 8 + i] + pmax;
        lpart[i] = 0.f;
        oacc[i][0] = 0.f; oacc[i][1] = 0.f;
    }

    for (int kt = 0; kt < N_; kt += 64) {
        // load K,V tile + pos_bias slice
#pragma unroll
        for (int i = 0; i < 4; i++) {
            int id = t + i * 128;
            int r = id >> 3, d4 = id & 7;
            *(float4*)&Ks[r][d4 * 4] = ((const float4*)Kp)[((size_t)(kt + r) * HD_) / 4 + d4];
            *(float4*)&Vs[r][d4 * 4] = ((const float4*)Vp)[((size_t)(kt + r) * HD_) / 4 + d4];
        }
        if (t < 64) pb[t] = pos_bias[(size_t)h * N_ + kt + t];
        __syncthreads();

        // ---- S = q.k^T (8x4 register tile, d vectorized) ----
        float acc[8][4];
#pragma unroll
        for (int i = 0; i < 8; i++)
#pragma unroll
            for (int j = 0; j < 4; j++) acc[i][j] = 0.f;

#pragma unroll
        for (int c = 0; c < 8; c++) {          // 8 float4 chunks of d
            float4 b4[4];
#pragma unroll
            for (int j = 0; j < 4; j++) b4[j] = *(const float4*)&Ks[tx * 4 + j][c * 4];
#pragma unroll
            for (int i = 0; i < 8; i++) {
                float4 a = *(const float4*)&qs[ty * 8 + i][c * 4];
#pragma unroll
                for (int j = 0; j < 4; j++)
                    acc[i][j] += a.x * b4[j].x + a.y * b4[j].y + a.z * b4[j].z + a.w * b4[j].w;
            }
        }

        // ---- exp with fixed bound, accumulate l, store P ----
        {
            float p0 = pb[tx * 4 + 0], p1 = pb[tx * 4 + 1];
            float p2 = pb[tx * 4 + 2], p3 = pb[tx * 4 + 3];
#pragma unroll
            for (int i = 0; i < 8; i++) {
                float4 e;
                e.x = __expf(acc[i][0] + p0 - mrow[i]);
                e.y = __expf(acc[i][1] + p1 - mrow[i]);
                e.z = __expf(acc[i][2] + p2 - mrow[i]);
                e.w = __expf(acc[i][3] + p3 - mrow[i]);
                lpart[i] += (e.x + e.y) + (e.z + e.w);
                *(float4*)&Ss[ty * 8 + i][tx * 4] = e;
            }
        }
        __syncthreads();

        // ---- O += P @ V (8 rows x 2 dims, kk vectorized by 4) ----
#pragma unroll
        for (int c = 0; c < 16; c++) {
            float2 v2[4];
#pragma unroll
            for (int j = 0; j < 4; j++) v2[j] = *(const float2*)&Vs[c * 4 + j][tx * 2];
#pragma unroll
            for (int i = 0; i < 8; i++) {
                float4 pp = *(const float4*)&Ss[ty * 8 + i][c * 4];
                oacc[i][0] += pp.x * v2[0].x + pp.y * v2[1].x + pp.z * v2[2].x + pp.w * v2[3].x;
                oacc[i][1] += pp.x * v2[0].y + pp.y * v2[1].y + pp.z * v2[2].y + pp.w * v2[3].y;
            }
        }
        __syncthreads();
    }

    // ---- reduce l across the 16 tx lanes sharing ty ----
#pragma unroll
    for (int i = 0; i < 8; i++) {
        float l = lpart[i];
#pragma unroll
        for (int o = 8; o; o >>= 1) l += __shfl_xor_sync(FULL, l, o);
        lpart[i] = l;
    }

    // ---- finalize ----
#pragma unroll
    for (int i = 0; i < 8; i++) {
        float inv = 1.f / lpart[i];
        int n = qbase + ty * 8 + i;
        float2 o2;
        o2.x = oacc[i][0] * inv;
        o2.y = oacc[i][1] * inv;
        *(float2*)&g_att[((size_t)(b * N_ + n)) * C_ + h * HD_ + tx * 2] = o2;
    }
}

// ---------------------------------------------------------------------------
extern "C" void kernel_launch(void* const* d_in, const int* in_sizes, int n_in,
                              void* d_out, int out_size) {
    const float* x      = (const float*)d_in[0];
    const float* q_w    = (const float*)d_in[1];
    const float* q_b    = (const float*)d_in[2];
    const float* kv_w   = (const float*)d_in[3];
    const float* kv_b   = (const float*)d_in[4];
    const float* qe     = (const float*)d_in[5];
    const float* temp   = (const float*)d_in[6];
    const float* pos_b  = (const float*)d_in[7];
    const float* proj_w = (const float*)d_in[8];
    const float* proj_b = (const float*)d_in[9];
    float* out = (float*)d_out;

    float *p_qtmp, *p_kvtmp, *p_att;
    cudaGetSymbolAddress((void**)&p_qtmp, g_qtmp);
    cudaGetSymbolAddress((void**)&p_kvtmp, g_kvtmp);
    cudaGetSymbolAddress((void**)&p_att, g_att);

    // 1) projections
    gemm_xwT_v2<<<dim3(C_ / 64, M_ / 64), 128>>>(x, q_w, q_b, p_qtmp, C_);
    gemm_xwT_v2<<<dim3(C2_ / 64, M_ / 64), 128>>>(x, kv_w, kv_b, p_kvtmp, C2_);
    // 2) pos_bias max per head
    pbmax_kernel<<<NH_, 256>>>(pos_b);
    // 3) normalize / embed / scale / relayout (+ ||q_row||)
    {
        int warps = B_ * N_ * NH_;
        qkv_epilogue_kernel<<<(warps + 7) / 8, 256>>>(temp, qe);
    }
    // 4) attention
    attn_v2<<<dim3(N_ / 64, B_ * NH_), 128>>>(pos_b);
    // 5) output projection into d_out
    gemm_xwT_v2<<<dim3(C_ / 64, M_ / 64), 128>>>(p_att, proj_w, proj_b, out, C_);
}

// round 7
// speedup vs baseline: 1.9180x; 1.3821x over previous
#include <cuda_runtime.h>
#include <math.h>

// Problem constants (fixed by the dataset)
constexpr int B_  = 2;
constexpr int N_  = 2048;
constexpr int C_  = 384;
constexpr int NH_ = 12;
constexpr int HD_ = 32;
constexpr int M_  = B_ * N_;     // 4096 tokens
constexpr int C2_ = 2 * C_;      // 768

// ---------------- scratch (device globals; no allocation allowed) ----------
__device__ float g_qtmp[M_ * C_];
__device__ float g_kvtmp[M_ * C2_];
__device__ float g_q[B_ * NH_ * N_ * HD_];
__device__ float g_k[B_ * NH_ * N_ * HD_];
__device__ float g_v[B_ * NH_ * N_ * HD_];
__device__ float g_att[M_ * C_];
__device__ float g_qmax[B_ * NH_ * N_];
__device__ float g_pbmax[NH_];

// ---------------- packed fp32x2 helpers (sm_100+ FFMA2) --------------------
__device__ __forceinline__ unsigned long long fma2(unsigned long long a,
                                                   unsigned long long b,
                                                   unsigned long long c) {
    unsigned long long d;
    asm("fma.rn.f32x2 %0, %1, %2, %3;" : "=l"(d) : "l"(a), "l"(b), "l"(c));
    return d;
}
__device__ __forceinline__ float2 unpack2(unsigned long long v) {
    float2 r;
    asm("mov.b64 {%0, %1}, %2;" : "=f"(r.x), "=f"(r.y) : "l"(v));
    return r;
}

// ---------------------------------------------------------------------------
// Projection GEMM: out[m][j] = sum_k X[m][k]*W[j][k] + b[j].  K = 384.
// 128 threads, 64x64 tile, BK=64. 8x4 register tile, k-parity packed FFMA2.
// Thread (ty,tx): rows ty*8..+7, cols {tx, tx+16, tx+32, tx+48}.
// ---------------------------------------------------------------------------
__global__ __launch_bounds__(128) void gemm_v3(const float* __restrict__ X,
                                               const float* __restrict__ W,
                                               const float* __restrict__ bias,
                                               float* __restrict__ out, int Nout) {
    __shared__ __align__(16) float Xs[64][68];
    __shared__ __align__(16) float Ws[64][68];
    const int bm = blockIdx.y * 64;
    const int bn = blockIdx.x * 64;
    const int t  = threadIdx.x;
    const int ty = t >> 4;
    const int tx = t & 15;

    unsigned long long acc2[8][4];
#pragma unroll
    for (int i = 0; i < 8; i++)
#pragma unroll
        for (int j = 0; j < 4; j++) acc2[i][j] = 0ull;

    for (int k0 = 0; k0 < C_; k0 += 64) {
#pragma unroll
        for (int i = 0; i < 8; i++) {
            int id = t + i * 128;
            int r  = id >> 4;
            int kc = id & 15;
            *(float4*)&Xs[r][kc * 4] =
                ((const float4*)X)[((size_t)(bm + r) * C_ + k0) / 4 + kc];
            *(float4*)&Ws[r][kc * 4] =
                ((const float4*)W)[((size_t)(bn + r) * C_ + k0) / 4 + kc];
        }
        __syncthreads();
#pragma unroll
        for (int c = 0; c < 16; c++) {
            ulonglong2 b2[4];
#pragma unroll
            for (int j = 0; j < 4; j++)
                b2[j] = *(const ulonglong2*)&Ws[tx + j * 16][c * 4];
#pragma unroll
            for (int i = 0; i < 8; i++) {
                ulonglong2 a = *(const ulonglong2*)&Xs[ty * 8 + i][c * 4];
#pragma unroll
                for (int j = 0; j < 4; j++) {
                    acc2[i][j] = fma2(a.x, b2[j].x, acc2[i][j]);
                    acc2[i][j] = fma2(a.y, b2[j].y, acc2[i][j]);
                }
            }
        }
        __syncthreads();
    }
#pragma unroll
    for (int i = 0; i < 8; i++) {
        int m = bm + ty * 8 + i;
#pragma unroll
        for (int j = 0; j < 4; j++) {
            int n = bn + tx + j * 16;
            float2 s = unpack2(acc2[i][j]);
            out[(size_t)m * Nout + n] = s.x + s.y + bias[n];
        }
    }
}

// ---------------------------------------------------------------------------
// per-head max of pos_bias
// ---------------------------------------------------------------------------
__global__ void pbmax_kernel(const float* __restrict__ pb) {
    __shared__ float red[256];
    int h = blockIdx.x, t = threadIdx.x;
    float m = -1e30f;
    for (int i = t; i < N_; i += 256) m = fmaxf(m, pb[(size_t)h * N_ + i]);
    red[t] = m;
    __syncthreads();
    for (int s = 128; s; s >>= 1) {
        if (t < s) red[t] = fmaxf(red[t], red[t + s]);
        __syncthreads();
    }
    if (t == 0) g_pbmax[h] = red[0];
}

// ---------------------------------------------------------------------------
// Epilogue: per (b,n,h) warp. L2-norm Q, add embedding, scale; L2-norm K;
// relayout to [bh][n][d]; store ||q_row|| for the softmax bound.
// ---------------------------------------------------------------------------
__global__ void qkv_epilogue_kernel(const float* __restrict__ temperature,
                                    const float* __restrict__ qe) {
    const int warp = blockIdx.x * (blockDim.x >> 5) + (threadIdx.x >> 5);
    const int lane = threadIdx.x & 31;
    if (warp >= B_ * N_ * NH_) return;
    const int h  = warp % NH_;
    const int bn = warp / NH_;
    const int n  = bn % N_;
    const int b  = bn / N_;
    const unsigned FULL = 0xFFFFFFFFu;

    float qv = g_qtmp[(size_t)bn * C_ + h * HD_ + lane];
    float ss = qv * qv;
#pragma unroll
    for (int o = 16; o; o >>= 1) ss += __shfl_xor_sync(FULL, ss, o);
    float denom = fmaxf(sqrtf(ss), 1e-12f);
    float scale = log1pf(expf(temperature[h])) * logf((float)N_);
    float qn = (qv / denom + qe[h * HD_ + lane]) * scale;
    size_t hi = ((size_t)(b * NH_ + h) * N_ + n) * HD_ + lane;
    g_q[hi] = qn;

    float ss3 = qn * qn;
#pragma unroll
    for (int o = 16; o; o >>= 1) ss3 += __shfl_xor_sync(FULL, ss3, o);
    if (lane == 0) g_qmax[(size_t)(b * NH_ + h) * N_ + n] = sqrtf(ss3);

    float kv = g_kvtmp[(size_t)bn * C2_ + h * HD_ + lane];
    float ss2 = kv * kv;
#pragma unroll
    for (int o = 16; o; o >>= 1) ss2 += __shfl_xor_sync(FULL, ss2, o);
    g_k[hi] = kv / fmaxf(sqrtf(ss2), 1e-12f);

    g_v[hi] = g_kvtmp[(size_t)bn * C2_ + C_ + h * HD_ + lane];
}

// ---------------------------------------------------------------------------
// Attention. CTA = 64 q rows of one (b,h), 128 threads, 64-key tiles.
// Fixed per-row softmax bound m = ||q_row|| + max(pos_bias[h]).
// S-GEMM : 8 rows x cols {tx,tx+16,tx+32,tx+48}, d-parity packed FFMA2.
// PV-GEMM: 8 rows x dims {2tx, 2tx+1}, kk-parity packed FFMA2 via
//          parity-interleaved V tile: Vp[kk/2][d*2 + (kk&1)].
// ---------------------------------------------------------------------------
__global__ __launch_bounds__(128, 3) void attn_v3(const float* __restrict__ pos_bias) {
    __shared__ __align__(16) float qs[64][36];
    __shared__ __align__(16) float Ks[64][36];
    __shared__ __align__(16) float Vp[32 * 64];     // [j=kk/2][d*2 + par]
    __shared__ __align__(16) float Ss[64][68];
    __shared__ float pb[64];

    const int bh    = blockIdx.y;
    const int h     = bh % NH_;
    const int b     = bh / NH_;
    const int qbase = blockIdx.x * 64;
    const int t     = threadIdx.x;
    const int ty    = t >> 4;
    const int tx    = t & 15;
    const unsigned FULL = 0xFFFFFFFFu;

    const float* Qp = g_q + (size_t)bh * N_ * HD_;
    const float* Kp = g_k + (size_t)bh * N_ * HD_;
    const float* Vp_g = g_v + (size_t)bh * N_ * HD_;

    // load q tile (64x32 = 512 float4)
#pragma unroll
    for (int i = 0; i < 4; i++) {
        int id = t + i * 128;
        int r = id >> 3, d4 = id & 7;
        *(float4*)&qs[r][d4 * 4] = ((const float4*)Qp)[((size_t)(qbase + r) * HD_) / 4 + d4];
    }

    float mrow[8], lpart[8];
    unsigned long long o0[8], o1[8];
    const float pmax = g_pbmax[h];
#pragma unroll
    for (int i = 0; i < 8; i++) {
        mrow[i] = g_qmax[(size_t)bh * N_ + qbase + ty * 8 + i] + pmax;
        lpart[i] = 0.f;
        o0[i] = 0ull; o1[i] = 0ull;
    }

    for (int kt = 0; kt < N_; kt += 64) {
        // ---- load K row-major; V parity-interleaved; pos_bias slice ----
#pragma unroll
        for (int i = 0; i < 4; i++) {
            int id = t + i * 128;
            int r = id >> 3, d4 = id & 7;
            *(float4*)&Ks[r][d4 * 4] = ((const float4*)Kp)[((size_t)(kt + r) * HD_) / 4 + d4];
            float4 v = ((const float4*)Vp_g)[((size_t)(kt + r) * HD_) / 4 + d4];
            float* vb = &Vp[(r >> 1) * 64 + (r & 1)];
            vb[(d4 * 4 + 0) * 2] = v.x;
            vb[(d4 * 4 + 1) * 2] = v.y;
            vb[(d4 * 4 + 2) * 2] = v.z;
            vb[(d4 * 4 + 3) * 2] = v.w;
        }
        if (t < 64) pb[t] = pos_bias[(size_t)h * N_ + kt + t];
        __syncthreads();

        // ---- S = q.k^T, d-parity packed ----
        unsigned long long acc2[8][4];
#pragma unroll
        for (int i = 0; i < 8; i++)
#pragma unroll
            for (int j = 0; j < 4; j++) acc2[i][j] = 0ull;

#pragma unroll
        for (int c = 0; c < 8; c++) {
            ulonglong2 b2[4];
#pragma unroll
            for (int j = 0; j < 4; j++)
                b2[j] = *(const ulonglong2*)&Ks[tx + j * 16][c * 4];
#pragma unroll
            for (int i = 0; i < 8; i++) {
                ulonglong2 a = *(const ulonglong2*)&qs[ty * 8 + i][c * 4];
#pragma unroll
                for (int j = 0; j < 4; j++) {
                    acc2[i][j] = fma2(a.x, b2[j].x, acc2[i][j]);
                    acc2[i][j] = fma2(a.y, b2[j].y, acc2[i][j]);
                }
            }
        }

        // ---- exp with fixed bound, accumulate l, store P ----
        {
            float pbv[4];
#pragma unroll
            for (int j = 0; j < 4; j++) pbv[j] = pb[tx + j * 16];
#pragma unroll
            for (int i = 0; i < 8; i++) {
#pragma unroll
                for (int j = 0; j < 4; j++) {
                    float2 s2 = unpack2(acc2[i][j]);
                    float e = __expf(s2.x + s2.y + pbv[j] - mrow[i]);
                    lpart[i] += e;
                    Ss[ty * 8 + i][tx + j * 16] = e;
                }
            }
        }
        __syncwarp();   // Ss rows are produced & consumed by the same half-warp

        // ---- O += P @ V, kk-parity packed ----
        {
            const int d0 = tx * 2;
#pragma unroll
            for (int c = 0; c < 16; c++) {        // kk = 4c..4c+3 -> j pairs 2c, 2c+1
                unsigned long long v00 = *(const unsigned long long*)&Vp[(2 * c + 0) * 64 + d0 * 2];
                unsigned long long v01 = *(const unsigned long long*)&Vp[(2 * c + 1) * 64 + d0 * 2];
                unsigned long long v10 = *(const unsigned long long*)&Vp[(2 * c + 0) * 64 + d0 * 2 + 2];
                unsigned long long v11 = *(const unsigned long long*)&Vp[(2 * c + 1) * 64 + d0 * 2 + 2];
#pragma unroll
                for (int i = 0; i < 8; i++) {
                    ulonglong2 p = *(const ulonglong2*)&Ss[ty * 8 + i][c * 4];
                    o0[i] = fma2(p.x, v00, o0[i]);
                    o0[i] = fma2(p.y, v01, o0[i]);
                    o1[i] = fma2(p.x, v10, o1[i]);
                    o1[i] = fma2(p.y, v11, o1[i]);
                }
            }
        }
        __syncthreads();
    }

    // ---- reduce l across the 16 tx lanes sharing ty ----
#pragma unroll
    for (int i = 0; i < 8; i++) {
        float l = lpart[i];
#pragma unroll
        for (int o = 8; o; o >>= 1) l += __shfl_xor_sync(FULL, l, o);
        lpart[i] = l;
    }

    // ---- finalize ----
#pragma unroll
    for (int i = 0; i < 8; i++) {
        float inv = 1.f / lpart[i];
        int n = qbase + ty * 8 + i;
        float2 a = unpack2(o0[i]);
        float2 bb = unpack2(o1[i]);
        float2 o2;
        o2.x = (a.x + a.y) * inv;
        o2.y = (bb.x + bb.y) * inv;
        *(float2*)&g_att[((size_t)(b * N_ + n)) * C_ + h * HD_ + tx * 2] = o2;
    }
}

// ---------------------------------------------------------------------------
extern "C" void kernel_launch(void* const* d_in, const int* in_sizes, int n_in,
                              void* d_out, int out_size) {
    const float* x      = (const float*)d_in[0];
    const float* q_w    = (const float*)d_in[1];
    const float* q_b    = (const float*)d_in[2];
    const float* kv_w   = (const float*)d_in[3];
    const float* kv_b   = (const float*)d_in[4];
    const float* qe     = (const float*)d_in[5];
    const float* temp   = (const float*)d_in[6];
    const float* pos_b  = (const float*)d_in[7];
    const float* proj_w = (const float*)d_in[8];
    const float* proj_b = (const float*)d_in[9];
    float* out = (float*)d_out;

    float *p_qtmp, *p_kvtmp, *p_att;
    cudaGetSymbolAddress((void**)&p_qtmp, g_qtmp);
    cudaGetSymbolAddress((void**)&p_kvtmp, g_kvtmp);
    cudaGetSymbolAddress((void**)&p_att, g_att);

    gemm_v3<<<dim3(C_ / 64, M_ / 64), 128>>>(x, q_w, q_b, p_qtmp, C_);
    gemm_v3<<<dim3(C2_ / 64, M_ / 64), 128>>>(x, kv_w, kv_b, p_kvtmp, C2_);
    pbmax_kernel<<<NH_, 256>>>(pos_b);
    {
        int warps = B_ * N_ * NH_;
        qkv_epilogue_kernel<<<(warps + 7) / 8, 256>>>(temp, qe);
    }
    attn_v3<<<dim3(N_ / 64, B_ * NH_), 128>>>(pos_b);
    gemm_v3<<<dim3(C_ / 64, M_ / 64), 128>>>(p_att, proj_w, proj_b, out, C_);
}

// round 9
// speedup vs baseline: 2.9067x; 1.5155x over previous
#include <cuda_runtime.h>
#include <cuda_bf16.h>
#include <math.h>
#include <stdint.h>

// Problem constants (fixed by the dataset)
constexpr int B_  = 2;
constexpr int N_  = 2048;
constexpr int C_  = 384;
constexpr int NH_ = 12;
constexpr int HD_ = 32;
constexpr int M_  = B_ * N_;     // 4096 tokens
constexpr int C2_ = 2 * C_;      // 768

// ---------------- scratch (device globals; no allocation allowed) ----------
__device__ float g_qtmp[M_ * C_];
__device__ float g_kvtmp[M_ * C2_];
__device__ float g_q[B_ * NH_ * N_ * HD_];
__device__ float g_k[B_ * NH_ * N_ * HD_];
__device__ float g_v[B_ * NH_ * N_ * HD_];
__device__ float g_att[M_ * C_];
__device__ float g_qmax[B_ * NH_ * N_];
__device__ float g_pbmax[NH_];

// ---------------- packed fp32x2 helpers (FFMA2) ----------------------------
__device__ __forceinline__ unsigned long long fma2(unsigned long long a,
                                                   unsigned long long b,
                                                   unsigned long long c) {
    unsigned long long d;
    asm("fma.rn.f32x2 %0, %1, %2, %3;" : "=l"(d) : "l"(a), "l"(b), "l"(c));
    return d;
}
__device__ __forceinline__ float2 unpack2(unsigned long long v) {
    float2 r;
    asm("mov.b64 {%0, %1}, %2;" : "=f"(r.x), "=f"(r.y) : "l"(v));
    return r;
}

// ---------------- mma.sync bf16 helpers ------------------------------------
__device__ __forceinline__ void mma16816(float* d, const uint32_t* a,
                                         const uint32_t* b) {
    asm volatile(
        "mma.sync.aligned.m16n8k16.row.col.f32.bf16.bf16.f32 "
        "{%0,%1,%2,%3}, {%4,%5,%6,%7}, {%8,%9}, {%0,%1,%2,%3};"
        : "+f"(d[0]), "+f"(d[1]), "+f"(d[2]), "+f"(d[3])
        : "r"(a[0]), "r"(a[1]), "r"(a[2]), "r"(a[3]), "r"(b[0]), "r"(b[1]));
}
// pack two floats as bf16x2 (x -> low, y -> high)
__device__ __forceinline__ uint32_t pack_bf2(float x, float y) {
    __nv_bfloat162 h = __floats2bfloat162_rn(x, y);
    return *(uint32_t*)&h;
}
__device__ __forceinline__ float bf_hi(float x) {
    return __bfloat162float(__float2bfloat16_rn(x));
}

// ---------------------------------------------------------------------------
// Projection GEMM (packed FFMA2), unchanged.
// ---------------------------------------------------------------------------
__global__ __launch_bounds__(128) void gemm_v3(const float* __restrict__ X,
                                               const float* __restrict__ W,
                                               const float* __restrict__ bias,
                                               float* __restrict__ out, int Nout) {
    __shared__ __align__(16) float Xs[64][68];
    __shared__ __align__(16) float Ws[64][68];
    const int bm = blockIdx.y * 64;
    const int bn = blockIdx.x * 64;
    const int t  = threadIdx.x;
    const int ty = t >> 4;
    const int tx = t & 15;

    unsigned long long acc2[8][4];
#pragma unroll
    for (int i = 0; i < 8; i++)
#pragma unroll
        for (int j = 0; j < 4; j++) acc2[i][j] = 0ull;

    for (int k0 = 0; k0 < C_; k0 += 64) {
#pragma unroll
        for (int i = 0; i < 8; i++) {
            int id = t + i * 128;
            int r  = id >> 4;
            int kc = id & 15;
            *(float4*)&Xs[r][kc * 4] =
                ((const float4*)X)[((size_t)(bm + r) * C_ + k0) / 4 + kc];
            *(float4*)&Ws[r][kc * 4] =
                ((const float4*)W)[((size_t)(bn + r) * C_ + k0) / 4 + kc];
        }
        __syncthreads();
#pragma unroll
        for (int c = 0; c < 16; c++) {
            ulonglong2 b2[4];
#pragma unroll
            for (int j = 0; j < 4; j++)
                b2[j] = *(const ulonglong2*)&Ws[tx + j * 16][c * 4];
#pragma unroll
            for (int i = 0; i < 8; i++) {
                ulonglong2 a = *(const ulonglong2*)&Xs[ty * 8 + i][c * 4];
#pragma unroll
                for (int j = 0; j < 4; j++) {
                    acc2[i][j] = fma2(a.x, b2[j].x, acc2[i][j]);
                    acc2[i][j] = fma2(a.y, b2[j].y, acc2[i][j]);
                }
            }
        }
        __syncthreads();
    }
#pragma unroll
    for (int i = 0; i < 8; i++) {
        int m = bm + ty * 8 + i;
#pragma unroll
        for (int j = 0; j < 4; j++) {
            int n = bn + tx + j * 16;
            float2 s = unpack2(acc2[i][j]);
            out[(size_t)m * Nout + n] = s.x + s.y + bias[n];
        }
    }
}

// ---------------------------------------------------------------------------
__global__ void pbmax_kernel(const float* __restrict__ pb) {
    __shared__ float red[256];
    int h = blockIdx.x, t = threadIdx.x;
    float m = -1e30f;
    for (int i = t; i < N_; i += 256) m = fmaxf(m, pb[(size_t)h * N_ + i]);
    red[t] = m;
    __syncthreads();
    for (int s = 128; s; s >>= 1) {
        if (t < s) red[t] = fmaxf(red[t], red[t + s]);
        __syncthreads();
    }
    if (t == 0) g_pbmax[h] = red[0];
}

// ---------------------------------------------------------------------------
__global__ void qkv_epilogue_kernel(const float* __restrict__ temperature,
                                    const float* __restrict__ qe) {
    const int warp = blockIdx.x * (blockDim.x >> 5) + (threadIdx.x >> 5);
    const int lane = threadIdx.x & 31;
    if (warp >= B_ * N_ * NH_) return;
    const int h  = warp % NH_;
    const int bn = warp / NH_;
    const int n  = bn % N_;
    const int b  = bn / N_;
    const unsigned FULL = 0xFFFFFFFFu;

    float qv = g_qtmp[(size_t)bn * C_ + h * HD_ + lane];
    float ss = qv * qv;
#pragma unroll
    for (int o = 16; o; o >>= 1) ss += __shfl_xor_sync(FULL, ss, o);
    float denom = fmaxf(sqrtf(ss), 1e-12f);
    float scale = log1pf(expf(temperature[h])) * logf((float)N_);
    float qn = (qv / denom + qe[h * HD_ + lane]) * scale;
    size_t hi = ((size_t)(b * NH_ + h) * N_ + n) * HD_ + lane;
    g_q[hi] = qn;

    float ss3 = qn * qn;
#pragma unroll
    for (int o = 16; o; o >>= 1) ss3 += __shfl_xor_sync(FULL, ss3, o);
    if (lane == 0) g_qmax[(size_t)(b * NH_ + h) * N_ + n] = sqrtf(ss3);

    float kv = g_kvtmp[(size_t)bn * C2_ + h * HD_ + lane];
    float ss2 = kv * kv;
#pragma unroll
    for (int o = 16; o; o >>= 1) ss2 += __shfl_xor_sync(FULL, ss2, o);
    g_k[hi] = kv / fmaxf(sqrtf(ss2), 1e-12f);

    g_v[hi] = g_kvtmp[(size_t)bn * C2_ + C_ + h * HD_ + lane];
}

// ---------------------------------------------------------------------------
// Tensor-core attention via mma.sync m16n8k16 bf16, split hi/lo (3 MMAs per
// product => ~fp32 accuracy). CTA = 64 q rows of one (b,h); 4 warps x 16 rows.
// Fixed per-row softmax bound (no online rescale). P stays in registers
// (C-layout -> A-layout repack). 64-key tiles.
// ---------------------------------------------------------------------------
constexpr int KST = 40;   // K/Q smem row stride (bf16 elems)
constexpr int VST = 72;   // Vt smem row stride (bf16 elems)

__global__ __launch_bounds__(128) void attn_mma(const float* __restrict__ pos_bias) {
    __shared__ __nv_bfloat16 Qh[64][KST], Ql[64][KST];
    __shared__ __nv_bfloat16 Kh[64][KST], Kl[64][KST];
    __shared__ __nv_bfloat16 Vth[32][VST], Vtl[32][VST];
    __shared__ float pb[64];

    const int t     = threadIdx.x;
    const int wid   = t >> 5;
    const int lane  = t & 31;
    const int bh    = blockIdx.y;
    const int h     = bh % NH_;
    const int b     = bh / NH_;
    const int qbase = blockIdx.x * 64;
    const unsigned FULL = 0xFFFFFFFFu;

    const float* Qp = g_q + (size_t)bh * N_ * HD_;
    const float* Kp = g_k + (size_t)bh * N_ * HD_;
    const float* Vp = g_v + (size_t)bh * N_ * HD_;

    // ---- fill Q tile (bf16 split) ----
#pragma unroll
    for (int i = 0; i < 4; i++) {
        int id = t + i * 128;
        int r = id >> 3, c4 = id & 7;        // row, float4-chunk of dims
        float4 v = ((const float4*)Qp)[(size_t)(qbase + r) * 8 + c4];
        float hx = bf_hi(v.x), hy = bf_hi(v.y), hz = bf_hi(v.z), hw = bf_hi(v.w);
        *(uint32_t*)&Qh[r][c4 * 4]     = pack_bf2(hx, hy);
        *(uint32_t*)&Qh[r][c4 * 4 + 2] = pack_bf2(hz, hw);
        *(uint32_t*)&Ql[r][c4 * 4]     = pack_bf2(v.x - hx, v.y - hy);
        *(uint32_t*)&Ql[r][c4 * 4 + 2] = pack_bf2(v.z - hz, v.w - hw);
    }
    __syncthreads();

    // ---- load Q fragments (persistent): ah/al[kstep][4] ----
    const int r0 = wid * 16 + (lane >> 2);   // warp-local row (0..7) + base
    const int qc = (lane & 3) * 2;
    uint32_t ah[2][4], al[2][4];
#pragma unroll
    for (int ks = 0; ks < 2; ks++) {
        int kb = ks * 16;
        ah[ks][0] = *(uint32_t*)&Qh[r0][kb + qc];
        ah[ks][1] = *(uint32_t*)&Qh[r0 + 8][kb + qc];
        ah[ks][2] = *(uint32_t*)&Qh[r0][kb + qc + 8];
        ah[ks][3] = *(uint32_t*)&Qh[r0 + 8][kb + qc + 8];
        al[ks][0] = *(uint32_t*)&Ql[r0][kb + qc];
        al[ks][1] = *(uint32_t*)&Ql[r0 + 8][kb + qc];
        al[ks][2] = *(uint32_t*)&Ql[r0][kb + qc + 8];
        al[ks][3] = *(uint32_t*)&Ql[r0 + 8][kb + qc + 8];
    }

    // softmax bound + row sums for the two rows this thread owns
    const float pmax = g_pbmax[h];
    const float mr0 = g_qmax[(size_t)bh * N_ + qbase + r0] + pmax;
    const float mr1 = g_qmax[(size_t)bh * N_ + qbase + r0 + 8] + pmax;
    float ls0 = 0.f, ls1 = 0.f;

    float oacc[4][4];                         // 4 dtiles x (c0..c3)
#pragma unroll
    for (int dt = 0; dt < 4; dt++)
#pragma unroll
        for (int j = 0; j < 4; j++) oacc[dt][j] = 0.f;

    for (int kt = 0; kt < N_; kt += 64) {
        if (kt > 0) __syncthreads();          // guard K/V reuse

        // ---- fill K tile (row-major split) + V tile (transposed split) ----
#pragma unroll
        for (int i = 0; i < 4; i++) {
            int id = t + i * 128;
            int r = id >> 3, c4 = id & 7;
            float4 kv4 = ((const float4*)Kp)[(size_t)(kt + r) * 8 + c4];
            float hx = bf_hi(kv4.x), hy = bf_hi(kv4.y),
                  hz = bf_hi(kv4.z), hw = bf_hi(kv4.w);
            *(uint32_t*)&Kh[r][c4 * 4]     = pack_bf2(hx, hy);
            *(uint32_t*)&Kh[r][c4 * 4 + 2] = pack_bf2(hz, hw);
            *(uint32_t*)&Kl[r][c4 * 4]     = pack_bf2(kv4.x - hx, kv4.y - hy);
            *(uint32_t*)&Kl[r][c4 * 4 + 2] = pack_bf2(kv4.z - hz, kv4.w - hw);

            float4 vv4 = ((const float4*)Vp)[(size_t)(kt + r) * 8 + c4];
            float vv[4] = {vv4.x, vv4.y, vv4.z, vv4.w};
#pragma unroll
            for (int j = 0; j < 4; j++) {
                int d = c4 * 4 + j;
                float hv = bf_hi(vv[j]);
                Vth[d][r] = __float2bfloat16_rn(hv);
                Vtl[d][r] = __float2bfloat16_rn(vv[j] - hv);
            }
        }
        if (t < 64) pb[t] = pos_bias[(size_t)h * N_ + kt + t];
        __syncthreads();

        // ---- S = Q.K^T over 8 n-tiles (keys), split 3-pass ----
        float sacc[8][4];
#pragma unroll
        for (int nt = 0; nt < 8; nt++) {
#pragma unroll
            for (int j = 0; j < 4; j++) sacc[nt][j] = 0.f;
            int kn = nt * 8 + (lane >> 2);    // key row for B frag
#pragma unroll
            for (int ks = 0; ks < 2; ks++) {
                int kb = ks * 16;
                uint32_t bhh[2], bll[2];
                bhh[0] = *(uint32_t*)&Kh[kn][kb + qc];
                bhh[1] = *(uint32_t*)&Kh[kn][kb + qc + 8];
                bll[0] = *(uint32_t*)&Kl[kn][kb + qc];
                bll[1] = *(uint32_t*)&Kl[kn][kb + qc + 8];
                mma16816(sacc[nt], ah[ks], bhh);
                mma16816(sacc[nt], ah[ks], bll);
                mma16816(sacc[nt], al[ks], bhh);
            }
        }

        // ---- softmax epilogue in registers; split P to bf16 hi/lo ----
        uint32_t ph2[8][2], pl2[8][2];
#pragma unroll
        for (int nt = 0; nt < 8; nt++) {
            float pc0 = pb[nt * 8 + qc], pc1 = pb[nt * 8 + qc + 1];
            float e0 = __expf(sacc[nt][0] + pc0 - mr0);
            float e1 = __expf(sacc[nt][1] + pc1 - mr0);
            float e2 = __expf(sacc[nt][2] + pc0 - mr1);
            float e3 = __expf(sacc[nt][3] + pc1 - mr1);
            ls0 += e0 + e1;
            ls1 += e2 + e3;
            float h0 = bf_hi(e0), h1 = bf_hi(e1), h2 = bf_hi(e2), h3 = bf_hi(e3);
            ph2[nt][0] = pack_bf2(h0, h1);
            ph2[nt][1] = pack_bf2(h2, h3);
            pl2[nt][0] = pack_bf2(e0 - h0, e1 - h1);
            pl2[nt][1] = pack_bf2(e2 - h2, e3 - h3);
        }

        // ---- O += P @ V : A = P (register repack), B = Vt ----
#pragma unroll
        for (int ks = 0; ks < 4; ks++) {
            uint32_t pah[4] = {ph2[2 * ks][0], ph2[2 * ks][1],
                               ph2[2 * ks + 1][0], ph2[2 * ks + 1][1]};
            uint32_t pal[4] = {pl2[2 * ks][0], pl2[2 * ks][1],
                               pl2[2 * ks + 1][0], pl2[2 * ks + 1][1]};
            int kb = ks * 16 + qc;            // key base for B frag
#pragma unroll
            for (int dt = 0; dt < 4; dt++) {
                int dn = dt * 8 + (lane >> 2);
                uint32_t vhh[2], vll[2];
                vhh[0] = *(uint32_t*)&Vth[dn][kb];
                vhh[1] = *(uint32_t*)&Vth[dn][kb + 8];
                vll[0] = *(uint32_t*)&Vtl[dn][kb];
                vll[1] = *(uint32_t*)&Vtl[dn][kb + 8];
                mma16816(oacc[dt], pah, vhh);
                mma16816(oacc[dt], pah, vll);
                mma16816(oacc[dt], pal, vhh);
            }
        }
    }

    // ---- reduce row sums across the quad (threads sharing a row) ----
#pragma unroll
    for (int o = 1; o <= 2; o <<= 1) {
        ls0 += __shfl_xor_sync(FULL, ls0, o);
        ls1 += __shfl_xor_sync(FULL, ls1, o);
    }
    const float inv0 = 1.f / ls0, inv1 = 1.f / ls1;

    // ---- write O: thread owns (r0, dt*8+qc..+1) and (r0+8, same) ----
    float* d0 = &g_att[(size_t)(b * N_ + qbase + r0) * C_ + h * HD_];
    float* d1 = &g_att[(size_t)(b * N_ + qbase + r0 + 8) * C_ + h * HD_];
#pragma unroll
    for (int dt = 0; dt < 4; dt++) {
        int dc = dt * 8 + qc;
        *(float2*)&d0[dc] = make_float2(oacc[dt][0] * inv0, oacc[dt][1] * inv0);
        *(float2*)&d1[dc] = make_float2(oacc[dt][2] * inv1, oacc[dt][3] * inv1);
    }
}

// ---------------------------------------------------------------------------
extern "C" void kernel_launch(void* const* d_in, const int* in_sizes, int n_in,
                              void* d_out, int out_size) {
    const float* x      = (const float*)d_in[0];
    const float* q_w    = (const float*)d_in[1];
    const float* q_b    = (const float*)d_in[2];
    const float* kv_w   = (const float*)d_in[3];
    const float* kv_b   = (const float*)d_in[4];
    const float* qe     = (const float*)d_in[5];
    const float* temp   = (const float*)d_in[6];
    const float* pos_b  = (const float*)d_in[7];
    const float* proj_w = (const float*)d_in[8];
    const float* proj_b = (const float*)d_in[9];
    float* out = (float*)d_out;

    float *p_qtmp, *p_kvtmp, *p_att;
    cudaGetSymbolAddress((void**)&p_qtmp, g_qtmp);
    cudaGetSymbolAddress((void**)&p_kvtmp, g_kvtmp);
    cudaGetSymbolAddress((void**)&p_att, g_att);

    gemm_v3<<<dim3(C_ / 64, M_ / 64), 128>>>(x, q_w, q_b, p_qtmp, C_);
    gemm_v3<<<dim3(C2_ / 64, M_ / 64), 128>>>(x, kv_w, kv_b, p_kvtmp, C2_);
    pbmax_kernel<<<NH_, 256>>>(pos_b);
    {
        int warps = B_ * N_ * NH_;
        qkv_epilogue_kernel<<<(warps + 7) / 8, 256>>>(temp, qe);
    }
    attn_mma<<<dim3(N_ / 64, B_ * NH_), 128>>>(pos_b);
    gemm_v3<<<dim3(C_ / 64, M_ / 64), 128>>>(p_att, proj_w, proj_b, out, C_);
}

// round 13
// speedup vs baseline: 3.7694x; 1.2968x over previous
#include <cuda_runtime.h>
#include <cuda_bf16.h>
#include <math.h>
#include <stdint.h>

// Problem constants (fixed by the dataset)
constexpr int B_  = 2;
constexpr int N_  = 2048;
constexpr int C_  = 384;
constexpr int NH_ = 12;
constexpr int HD_ = 32;
constexpr int M_  = B_ * N_;     // 4096 tokens
constexpr int C2_ = 2 * C_;      // 768
constexpr int BHN = B_ * NH_ * N_ * HD_;

// ---------------- scratch (device globals; no allocation allowed) ----------
__device__ float g_qtmp[M_ * C_];
__device__ float g_kvtmp[M_ * C2_];
__device__ float g_qmax[B_ * NH_ * N_];
__device__ float g_pbmax[NH_];

__device__ __nv_bfloat16 g_xh[M_ * C_],  g_xl[M_ * C_];
__device__ __nv_bfloat16 g_wqh[C_ * C_], g_wql[C_ * C_];
__device__ __nv_bfloat16 g_wkvh[C2_ * C_], g_wkvl[C2_ * C_];
__device__ __nv_bfloat16 g_wph[C_ * C_], g_wpl[C_ * C_];
__device__ __nv_bfloat16 g_qh[BHN], g_ql[BHN];       // [bh][n][d]
__device__ __nv_bfloat16 g_kh[BHN], g_kl[BHN];       // [bh][n][d]
__device__ __nv_bfloat16 g_vth[BHN], g_vtl[BHN];     // [bh][d][n] (transposed)
__device__ __nv_bfloat16 g_atth[M_ * C_], g_attl[M_ * C_];

// ---------------- helpers ---------------------------------------------------
__device__ __forceinline__ void mma16816(float* d, const uint32_t* a,
                                         const uint32_t* b) {
    asm volatile(
        "mma.sync.aligned.m16n8k16.row.col.f32.bf16.bf16.f32 "
        "{%0,%1,%2,%3}, {%4,%5,%6,%7}, {%8,%9}, {%0,%1,%2,%3};"
        : "+f"(d[0]), "+f"(d[1]), "+f"(d[2]), "+f"(d[3])
        : "r"(a[0]), "r"(a[1]), "r"(a[2]), "r"(a[3]), "r"(b[0]), "r"(b[1]));
}
__device__ __forceinline__ uint32_t pack_bf2(float x, float y) {
    __nv_bfloat162 h = __floats2bfloat162_rn(x, y);
    return *(uint32_t*)&h;
}
__device__ __forceinline__ float bf_hi(float x) {
    return __bfloat162float(__float2bfloat16_rn(x));
}

// ---------------------------------------------------------------------------
// Split fp32 array into bf16 hi/lo (vectorized by 4)
// ---------------------------------------------------------------------------
__global__ void conv_split(const float* __restrict__ in,
                           __nv_bfloat16* __restrict__ hi,
                           __nv_bfloat16* __restrict__ lo, int n4) {
    int i = blockIdx.x * blockDim.x + threadIdx.x;
    if (i >= n4) return;
    float4 v = ((const float4*)in)[i];
    float hx = bf_hi(v.x), hy = bf_hi(v.y), hz = bf_hi(v.z), hw = bf_hi(v.w);
    ((uint2*)hi)[i] = make_uint2(pack_bf2(hx, hy), pack_bf2(hz, hw));
    ((uint2*)lo)[i] = make_uint2(pack_bf2(v.x - hx, v.y - hy),
                                 pack_bf2(v.z - hz, v.w - hw));
}

// ---------------------------------------------------------------------------
// Tensor-core projection GEMM: out[m][j] = sum_k X[m][k]*W[j][k] + bias[j]
// Split bf16, 3 MMAs per product. 64x64 tile, BK=32, 128 threads.
// ---------------------------------------------------------------------------
__global__ __launch_bounds__(128) void gemm_tc(
    const __nv_bfloat16* __restrict__ Xh, const __nv_bfloat16* __restrict__ Xl,
    const __nv_bfloat16* __restrict__ Wh, const __nv_bfloat16* __restrict__ Wl,
    const float* __restrict__ bias, float* __restrict__ out, int Nout) {
    __shared__ __nv_bfloat16 Ah[64][40], Al[64][40];
    __shared__ __nv_bfloat16 Bh[64][40], Bl[64][40];

    const int bm = blockIdx.y * 64;
    const int bn = blockIdx.x * 64;
    const int t  = threadIdx.x;
    const int wid  = t >> 5;
    const int lane = t & 31;
    const int r0 = wid * 16 + (lane >> 2);
    const int qc = (lane & 3) * 2;

    float acc[8][4];
#pragma unroll
    for (int nt = 0; nt < 8; nt++)
#pragma unroll
        for (int j = 0; j < 4; j++) acc[nt][j] = 0.f;

    for (int k0 = 0; k0 < C_; k0 += 32) {
        if (k0 > 0) __syncthreads();
#pragma unroll
        for (int i = 0; i < 2; i++) {
            int id = t + i * 128;
            int r = id >> 2, c = id & 3;      // 64 rows x 4 uint4
            *(uint4*)&Ah[r][c * 8] = *(const uint4*)&Xh[(size_t)(bm + r) * C_ + k0 + c * 8];
            *(uint4*)&Al[r][c * 8] = *(const uint4*)&Xl[(size_t)(bm + r) * C_ + k0 + c * 8];
            *(uint4*)&Bh[r][c * 8] = *(const uint4*)&Wh[(size_t)(bn + r) * C_ + k0 + c * 8];
            *(uint4*)&Bl[r][c * 8] = *(const uint4*)&Wl[(size_t)(bn + r) * C_ + k0 + c * 8];
        }
        __syncthreads();

#pragma unroll
        for (int ks = 0; ks < 2; ks++) {
            int kb = ks * 16;
            uint32_t ah[4], al[4];
            ah[0] = *(uint32_t*)&Ah[r0][kb + qc];
            ah[1] = *(uint32_t*)&Ah[r0 + 8][kb + qc];
            ah[2] = *(uint32_t*)&Ah[r0][kb + qc + 8];
            ah[3] = *(uint32_t*)&Ah[r0 + 8][kb + qc + 8];
            al[0] = *(uint32_t*)&Al[r0][kb + qc];
            al[1] = *(uint32_t*)&Al[r0 + 8][kb + qc];
            al[2] = *(uint32_t*)&Al[r0][kb + qc + 8];
            al[3] = *(uint32_t*)&Al[r0 + 8][kb + qc + 8];
#pragma unroll
            for (int nt = 0; nt < 8; nt++) {
                int kn = nt * 8 + (lane >> 2);
                uint32_t bhh[2], bll[2];
                bhh[0] = *(uint32_t*)&Bh[kn][kb + qc];
                bhh[1] = *(uint32_t*)&Bh[kn][kb + qc + 8];
                bll[0] = *(uint32_t*)&Bl[kn][kb + qc];
                bll[1] = *(uint32_t*)&Bl[kn][kb + qc + 8];
                mma16816(acc[nt], ah, bhh);
                mma16816(acc[nt], ah, bll);
                mma16816(acc[nt], al, bhh);
            }
        }
    }

#pragma unroll
    for (int nt = 0; nt < 8; nt++) {
        int n = bn + nt * 8 + qc;
        float2 bv = *(const float2*)&bias[n];
        *(float2*)&out[(size_t)(bm + r0) * Nout + n] =
            make_float2(acc[nt][0] + bv.x, acc[nt][1] + bv.y);
        *(float2*)&out[(size_t)(bm + r0 + 8) * Nout + n] =
            make_float2(acc[nt][2] + bv.x, acc[nt][3] + bv.y);
    }
}

// ---------------------------------------------------------------------------
__global__ void pbmax_kernel(const float* __restrict__ pb) {
    __shared__ float red[256];
    int h = blockIdx.x, t = threadIdx.x;
    float m = -1e30f;
    for (int i = t; i < N_; i += 256) m = fmaxf(m, pb[(size_t)h * N_ + i]);
    red[t] = m;
    __syncthreads();
    for (int s = 128; s; s >>= 1) {
        if (t < s) red[t] = fmaxf(red[t], red[t + s]);
        __syncthreads();
    }
    if (t == 0) g_pbmax[h] = red[0];
}

// ---------------------------------------------------------------------------
// Epilogue: per (b,n,h) warp. L2-norm Q (+embed+scale) and K; write split
// bf16 directly; store ||q_row||.
// ---------------------------------------------------------------------------
__global__ void qkv_epilogue_kernel(const float* __restrict__ temperature,
                                    const float* __restrict__ qe) {
    const int warp = blockIdx.x * (blockDim.x >> 5) + (threadIdx.x >> 5);
    const int lane = threadIdx.x & 31;
    if (warp >= B_ * N_ * NH_) return;
    const int h  = warp % NH_;
    const int bn = warp / NH_;
    const int n  = bn % N_;
    const int b  = bn / N_;
    const unsigned FULL = 0xFFFFFFFFu;

    float qv = g_qtmp[(size_t)bn * C_ + h * HD_ + lane];
    float ss = qv * qv;
#pragma unroll
    for (int o = 16; o; o >>= 1) ss += __shfl_xor_sync(FULL, ss, o);
    float denom = fmaxf(sqrtf(ss), 1e-12f);
    float scale = log1pf(expf(temperature[h])) * logf((float)N_);
    float qn = (qv / denom + qe[h * HD_ + lane]) * scale;
    size_t hi = ((size_t)(b * NH_ + h) * N_ + n) * HD_ + lane;
    __nv_bfloat16 qh16 = __float2bfloat16_rn(qn);
    g_qh[hi] = qh16;
    g_ql[hi] = __float2bfloat16_rn(qn - __bfloat162float(qh16));

    float ss3 = qn * qn;
#pragma unroll
    for (int o = 16; o; o >>= 1) ss3 += __shfl_xor_sync(FULL, ss3, o);
    if (lane == 0) g_qmax[(size_t)(b * NH_ + h) * N_ + n] = sqrtf(ss3);

    float kv = g_kvtmp[(size_t)bn * C2_ + h * HD_ + lane];
    float ss2 = kv * kv;
#pragma unroll
    for (int o = 16; o; o >>= 1) ss2 += __shfl_xor_sync(FULL, ss2, o);
    float kn = kv / fmaxf(sqrtf(ss2), 1e-12f);
    __nv_bfloat16 kh16 = __float2bfloat16_rn(kn);
    g_kh[hi] = kh16;
    g_kl[hi] = __float2bfloat16_rn(kn - __bfloat162float(kh16));
}

// ---------------------------------------------------------------------------
// V transpose + split: kvtmp[...,C:] (b,n,h,d) -> g_vth/g_vtl [bh][d][n]
// CTA = one (bh, 64-token chunk).
// ---------------------------------------------------------------------------
__global__ __launch_bounds__(128) void vtrans_kernel() {
    __shared__ float Vt[32][65];
    const int bh = blockIdx.y;
    const int nb = blockIdx.x * 64;
    const int b = bh / NH_, h = bh % NH_;
    const int t = threadIdx.x;

#pragma unroll
    for (int i = 0; i < 4; i++) {
        int id = t + i * 128;
        int r = id >> 3, c4 = id & 7;
        float4 v = *(const float4*)&g_kvtmp[(size_t)(b * N_ + nb + r) * C2_ + C_ +
                                            h * HD_ + c4 * 4];
        Vt[c4 * 4 + 0][r] = v.x;
        Vt[c4 * 4 + 1][r] = v.y;
        Vt[c4 * 4 + 2][r] = v.z;
        Vt[c4 * 4 + 3][r] = v.w;
    }
    __syncthreads();
#pragma unroll
    for (int i = 0; i < 16; i++) {
        int id = t + i * 128;
        int d = id >> 6, r = id & 63;
        float v = Vt[d][r];
        float hv = bf_hi(v);
        size_t o = (size_t)(bh * HD_ + d) * N_ + nb + r;
        g_vth[o] = __float2bfloat16_rn(hv);
        g_vtl[o] = __float2bfloat16_rn(v - hv);
    }
}

// ---------------------------------------------------------------------------
// Tensor-core attention (split bf16, all operands precomputed).
// CTA = 64 q rows of one (b,h); 4 warps x 16 rows; 64-key tiles.
// Tile fill is pure uint4 copies; Q frags loaded once from gmem.
// Output written directly as split bf16 for the output projection.
// ---------------------------------------------------------------------------
constexpr int KST = 40;
constexpr int VST = 72;

__global__ __launch_bounds__(128) void attn_mma(const float* __restrict__ pos_bias) {
    __shared__ __nv_bfloat16 Kh[64][KST], Kl[64][KST];
    __shared__ __nv_bfloat16 Vth[32][VST], Vtl[32][VST];
    __shared__ float pb[64];

    const int t     = threadIdx.x;
    const int wid   = t >> 5;
    const int lane  = t & 31;
    const int bh    = blockIdx.y;
    const int h     = bh % NH_;
    const int b     = bh / NH_;
    const int qbase = blockIdx.x * 64;
    const unsigned FULL = 0xFFFFFFFFu;

    const __nv_bfloat16* Qh_g = g_qh + (size_t)bh * N_ * HD_;
    const __nv_bfloat16* Ql_g = g_ql + (size_t)bh * N_ * HD_;
    const __nv_bfloat16* Kh_g = g_kh + (size_t)bh * N_ * HD_;
    const __nv_bfloat16* Kl_g = g_kl + (size_t)bh * N_ * HD_;
    const __nv_bfloat16* Vh_g = g_vth + (size_t)bh * HD_ * N_;
    const __nv_bfloat16* Vl_g = g_vtl + (size_t)bh * HD_ * N_;

    const int r0 = wid * 16 + (lane >> 2);
    const int qc = (lane & 3) * 2;

    // ---- Q fragments straight from gmem (persistent) ----
    uint32_t ah[2][4], al[2][4];
#pragma unroll
    for (int ks = 0; ks < 2; ks++) {
        int kb = ks * 16;
        ah[ks][0] = *(const uint32_t*)&Qh_g[(size_t)(qbase + r0) * HD_ + kb + qc];
        ah[ks][1] = *(const uint32_t*)&Qh_g[(size_t)(qbase + r0 + 8) * HD_ + kb + qc];
        ah[ks][2] = *(const uint32_t*)&Qh_g[(size_t)(qbase + r0) * HD_ + kb + qc + 8];
        ah[ks][3] = *(const uint32_t*)&Qh_g[(size_t)(qbase + r0 + 8) * HD_ + kb + qc + 8];
        al[ks][0] = *(const uint32_t*)&Ql_g[(size_t)(qbase + r0) * HD_ + kb + qc];
        al[ks][1] = *(const uint32_t*)&Ql_g[(size_t)(qbase + r0 + 8) * HD_ + kb + qc];
        al[ks][2] = *(const uint32_t*)&Ql_g[(size_t)(qbase + r0) * HD_ + kb + qc + 8];
        al[ks][3] = *(const uint32_t*)&Ql_g[(size_t)(qbase + r0 + 8) * HD_ + kb + qc + 8];
    }

    const float pmax = g_pbmax[h];
    const float mr0 = g_qmax[(size_t)bh * N_ + qbase + r0] + pmax;
    const float mr1 = g_qmax[(size_t)bh * N_ + qbase + r0 + 8] + pmax;
    float ls0 = 0.f, ls1 = 0.f;

    float oacc[4][4];
#pragma unroll
    for (int dt = 0; dt < 4; dt++)
#pragma unroll
        for (int j = 0; j < 4; j++) oacc[dt][j] = 0.f;

    for (int kt = 0; kt < N_; kt += 64) {
        if (kt > 0) __syncthreads();

        // ---- tile fill: pure vector copies ----
#pragma unroll
        for (int i = 0; i < 2; i++) {
            int id = t + i * 128;
            {   // K tiles: 64 rows x 4 uint4
                int r = id >> 2, c = id & 3;
                *(uint4*)&Kh[r][c * 8] =
                    *(const uint4*)&Kh_g[(size_t)(kt + r) * HD_ + c * 8];
                *(uint4*)&Kl[r][c * 8] =
                    *(const uint4*)&Kl_g[(size_t)(kt + r) * HD_ + c * 8];
            }
            {   // Vt tiles: 32 rows x 8 uint4
                int d = id >> 3, c = id & 7;
                *(uint4*)&Vth[d][c * 8] =
                    *(const uint4*)&Vh_g[(size_t)d * N_ + kt + c * 8];
                *(uint4*)&Vtl[d][c * 8] =
                    *(const uint4*)&Vl_g[(size_t)d * N_ + kt + c * 8];
            }
        }
        if (t < 64) pb[t] = pos_bias[(size_t)h * N_ + kt + t];
        __syncthreads();

        // ---- S = Q.K^T over 8 n-tiles, split 3-pass ----
        float sacc[8][4];
#pragma unroll
        for (int nt = 0; nt < 8; nt++) {
#pragma unroll
            for (int j = 0; j < 4; j++) sacc[nt][j] = 0.f;
            int kn = nt * 8 + (lane >> 2);
#pragma unroll
            for (int ks = 0; ks < 2; ks++) {
                int kb = ks * 16;
                uint32_t bhh[2], bll[2];
                bhh[0] = *(uint32_t*)&Kh[kn][kb + qc];
                bhh[1] = *(uint32_t*)&Kh[kn][kb + qc + 8];
                bll[0] = *(uint32_t*)&Kl[kn][kb + qc];
                bll[1] = *(uint32_t*)&Kl[kn][kb + qc + 8];
                mma16816(sacc[nt], ah[ks], bhh);
                mma16816(sacc[nt], ah[ks], bll);
                mma16816(sacc[nt], al[ks], bhh);
            }
        }

        // ---- softmax epilogue in registers; split P ----
        uint32_t ph2[8][2], pl2[8][2];
#pragma unroll
        for (int nt = 0; nt < 8; nt++) {
            float pc0 = pb[nt * 8 + qc], pc1 = pb[nt * 8 + qc + 1];
            float e0 = __expf(sacc[nt][0] + pc0 - mr0);
            float e1 = __expf(sacc[nt][1] + pc1 - mr0);
            float e2 = __expf(sacc[nt][2] + pc0 - mr1);
            float e3 = __expf(sacc[nt][3] + pc1 - mr1);
            ls0 += e0 + e1;
            ls1 += e2 + e3;
            float h0 = bf_hi(e0), h1 = bf_hi(e1), h2 = bf_hi(e2), h3 = bf_hi(e3);
            ph2[nt][0] = pack_bf2(h0, h1);
            ph2[nt][1] = pack_bf2(h2, h3);
            pl2[nt][0] = pack_bf2(e0 - h0, e1 - h1);
            pl2[nt][1] = pack_bf2(e2 - h2, e3 - h3);
        }

        // ---- O += P @ V ----
#pragma unroll
        for (int ks = 0; ks < 4; ks++) {
            uint32_t pah[4] = {ph2[2 * ks][0], ph2[2 * ks][1],
                               ph2[2 * ks + 1][0], ph2[2 * ks + 1][1]};
            uint32_t pal[4] = {pl2[2 * ks][0], pl2[2 * ks][1],
                               pl2[2 * ks + 1][0], pl2[2 * ks + 1][1]};
            int kb = ks * 16 + qc;
#pragma unroll
            for (int dt = 0; dt < 4; dt++) {
                int dn = dt * 8 + (lane >> 2);
                uint32_t vhh[2], vll[2];
                vhh[0] = *(uint32_t*)&Vth[dn][kb];
                vhh[1] = *(uint32_t*)&Vth[dn][kb + 8];
                vll[0] = *(uint32_t*)&Vtl[dn][kb];
                vll[1] = *(uint32_t*)&Vtl[dn][kb + 8];
                mma16816(oacc[dt], pah, vhh);
                mma16816(oacc[dt], pah, vll);
                mma16816(oacc[dt], pal, vhh);
            }
        }
    }

    // ---- reduce row sums across the quad ----
#pragma unroll
    for (int o = 1; o <= 2; o <<= 1) {
        ls0 += __shfl_xor_sync(FULL, ls0, o);
        ls1 += __shfl_xor_sync(FULL, ls1, o);
    }
    const float inv0 = 1.f / ls0, inv1 = 1.f / ls1;

    // ---- write O as split bf16 (feeds output projection) ----
    size_t o0 = (size_t)(b * N_ + qbase + r0) * C_ + h * HD_;
    size_t o1 = (size_t)(b * N_ + qbase + r0 + 8) * C_ + h * HD_;
#pragma unroll
    for (int dt = 0; dt < 4; dt++) {
        int dc = dt * 8 + qc;
        float a0 = oacc[dt][0] * inv0, a1 = oacc[dt][1] * inv0;
        float b0 = oacc[dt][2] * inv1, b1 = oacc[dt][3] * inv1;
        float h0 = bf_hi(a0), h1 = bf_hi(a1), h2 = bf_hi(b0), h3 = bf_hi(b1);
        *(uint32_t*)&g_atth[o0 + dc] = pack_bf2(h0, h1);
        *(uint32_t*)&g_attl[o0 + dc] = pack_bf2(a0 - h0, a1 - h1);
        *(uint32_t*)&g_atth[o1 + dc] = pack_bf2(h2, h3);
        *(uint32_t*)&g_attl[o1 + dc] = pack_bf2(b0 - h2, b1 - h3);
    }
}

// ---------------------------------------------------------------------------
extern "C" void kernel_launch(void* const* d_in, const int* in_sizes, int n_in,
                              void* d_out, int out_size) {
    const float* x      = (const float*)d_in[0];
    const float* q_w    = (const float*)d_in[1];
    const float* q_b    = (const float*)d_in[2];
    const float* kv_w   = (const float*)d_in[3];
    const float* kv_b   = (const float*)d_in[4];
    const float* qe     = (const float*)d_in[5];
    const float* temp   = (const float*)d_in[6];
    const float* pos_b  = (const float*)d_in[7];
    const float* proj_w = (const float*)d_in[8];
    const float* proj_b = (const float*)d_in[9];
    float* out = (float*)d_out;

    float *p_qtmp, *p_kvtmp;
    __nv_bfloat16 *p_xh, *p_xl, *p_wqh, *p_wql, *p_wkvh, *p_wkvl,
                  *p_wph, *p_wpl, *p_atth, *p_attl;
    cudaGetSymbolAddress((void**)&p_qtmp, g_qtmp);
    cudaGetSymbolAddress((void**)&p_kvtmp, g_kvtmp);
    cudaGetSymbolAddress((void**)&p_xh, g_xh);
    cudaGetSymbolAddress((void**)&p_xl, g_xl);
    cudaGetSymbolAddress((void**)&p_wqh, g_wqh);
    cudaGetSymbolAddress((void**)&p_wql, g_wql);
    cudaGetSymbolAddress((void**)&p_wkvh, g_wkvh);
    cudaGetSymbolAddress((void**)&p_wkvl, g_wkvl);
    cudaGetSymbolAddress((void**)&p_wph, g_wph);
    cudaGetSymbolAddress((void**)&p_wpl, g_wpl);
    cudaGetSymbolAddress((void**)&p_atth, g_atth);
    cudaGetSymbolAddress((void**)&p_attl, g_attl);

    // split conversions (x + weights)
    conv_split<<<(M_ * C_ / 4 + 255) / 256, 256>>>(x, p_xh, p_xl, M_ * C_ / 4);
    conv_split<<<(C_ * C_ / 4 + 255) / 256, 256>>>(q_w, p_wqh, p_wql, C_ * C_ / 4);
    conv_split<<<(C2_ * C_ / 4 + 255) / 256, 256>>>(kv_w, p_wkvh, p_wkvl, C2_ * C_ / 4);
    conv_split<<<(C_ * C_ / 4 + 255) / 256, 256>>>(proj_w, p_wph, p_wpl, C_ * C_ / 4);

    // projections on tensor cores
    gemm_tc<<<dim3(C_ / 64, M_ / 64), 128>>>(p_xh, p_xl, p_wqh, p_wql, q_b, p_qtmp, C_);
    gemm_tc<<<dim3(C2_ / 64, M_ / 64), 128>>>(p_xh, p_xl, p_wkvh, p_wkvl, kv_b, p_kvtmp, C2_);

    pbmax_kernel<<<NH_, 256>>>(pos_b);
    {
        int warps = B_ * N_ * NH_;
        qkv_epilogue_kernel<<<(warps + 7) / 8, 256>>>(temp, qe);
    }
    vtrans_kernel<<<dim3(N_ / 64, B_ * NH_), 128>>>();

    attn_mma<<<dim3(N_ / 64, B_ * NH_), 128>>>(pos_b);

    gemm_tc<<<dim3(C_ / 64, M_ / 64), 128>>>(p_atth, p_attl, p_wph, p_wpl, proj_b, out, C_);
}

// round 14
// speedup vs baseline: 4.2898x; 1.1381x over previous
#include <cuda_runtime.h>
#include <cuda_bf16.h>
#include <math.h>
#include <stdint.h>

// Problem constants (fixed by the dataset)
constexpr int B_  = 2;
constexpr int N_  = 2048;
constexpr int C_  = 384;
constexpr int NH_ = 12;
constexpr int HD_ = 32;
constexpr int M_  = B_ * N_;     // 4096 tokens
constexpr int C2_ = 2 * C_;      // 768
constexpr int BHN = B_ * NH_ * N_ * HD_;

// ---------------- scratch (device globals; no allocation allowed) ----------
__device__ float g_qtmp[M_ * C_];
__device__ float g_kvtmp[M_ * C2_];
__device__ float g_qmax[B_ * NH_ * N_];
__device__ float g_pbmax[NH_];

__device__ __nv_bfloat16 g_xh[M_ * C_],  g_xl[M_ * C_];
__device__ __nv_bfloat16 g_wqh[C_ * C_], g_wql[C_ * C_];
__device__ __nv_bfloat16 g_wkvh[C2_ * C_], g_wkvl[C2_ * C_];
__device__ __nv_bfloat16 g_wph[C_ * C_], g_wpl[C_ * C_];
__device__ __nv_bfloat16 g_qh[BHN], g_ql[BHN];       // [bh][n][d]
__device__ __nv_bfloat16 g_kh[BHN], g_kl[BHN];       // [bh][n][d]
__device__ __nv_bfloat16 g_vth[BHN], g_vtl[BHN];     // [bh][d][n] (transposed)
__device__ __nv_bfloat16 g_atth[M_ * C_], g_attl[M_ * C_];

// ---------------- helpers ---------------------------------------------------
__device__ __forceinline__ void mma16816(float* d, const uint32_t* a,
                                         const uint32_t* b) {
    asm volatile(
        "mma.sync.aligned.m16n8k16.row.col.f32.bf16.bf16.f32 "
        "{%0,%1,%2,%3}, {%4,%5,%6,%7}, {%8,%9}, {%0,%1,%2,%3};"
        : "+f"(d[0]), "+f"(d[1]), "+f"(d[2]), "+f"(d[3])
        : "r"(a[0]), "r"(a[1]), "r"(a[2]), "r"(a[3]), "r"(b[0]), "r"(b[1]));
}
__device__ __forceinline__ uint32_t pack_bf2(float x, float y) {
    __nv_bfloat162 h = __floats2bfloat162_rn(x, y);
    return *(uint32_t*)&h;
}
__device__ __forceinline__ float bf_hi(float x) {
    return __bfloat162float(__float2bfloat16_rn(x));
}
__device__ __forceinline__ void cp16(uint32_t sdst, const void* gsrc) {
    asm volatile("cp.async.cg.shared.global [%0], [%1], 16;"
                 :: "r"(sdst), "l"(gsrc));
}
#define CP_COMMIT() asm volatile("cp.async.commit_group;" ::: "memory")
#define CP_WAIT1()  asm volatile("cp.async.wait_group 1;" ::: "memory")

// ---------------------------------------------------------------------------
// Split all fp32 source arrays into bf16 hi/lo in ONE launch.
// ---------------------------------------------------------------------------
constexpr int SPL1 = M_ * C_ / 4;            // x
constexpr int SPL2 = SPL1 + C_ * C_ / 4;     // q_w
constexpr int SPL3 = SPL2 + C2_ * C_ / 4;    // kv_w
constexpr int SPL4 = SPL3 + C_ * C_ / 4;     // proj_w

__global__ void conv_split_all(const float* __restrict__ x,
                               const float* __restrict__ qw,
                               const float* __restrict__ kvw,
                               const float* __restrict__ pw) {
    int i = blockIdx.x * blockDim.x + threadIdx.x;
    const float* src;
    __nv_bfloat16 *hi, *lo;
    int j;
    if (i < SPL1)      { src = x;   hi = g_xh;  lo = g_xl;  j = i; }
    else if (i < SPL2) { src = qw;  hi = g_wqh; lo = g_wql; j = i - SPL1; }
    else if (i < SPL3) { src = kvw; hi = g_wkvh; lo = g_wkvl; j = i - SPL2; }
    else if (i < SPL4) { src = pw;  hi = g_wph; lo = g_wpl; j = i - SPL3; }
    else return;
    float4 v = ((const float4*)src)[j];
    float hx = bf_hi(v.x), hy = bf_hi(v.y), hz = bf_hi(v.z), hw = bf_hi(v.w);
    ((uint2*)hi)[j] = make_uint2(pack_bf2(hx, hy), pack_bf2(hz, hw));
    ((uint2*)lo)[j] = make_uint2(pack_bf2(v.x - hx, v.y - hy),
                                 pack_bf2(v.z - hz, v.w - hw));
}

// ---------------------------------------------------------------------------
// Tensor-core projection GEMM with 3-stage cp.async pipeline.
// out[m][j] = sum_k X[m][k]*W[j][k] + bias[j]; BK=32; 64x64 tile; 128 thr.
// Stage layout (bytes): Ah 5120 | Al 5120 | Bh 5120 | Bl 5120  (rows of 40 bf16)
// ---------------------------------------------------------------------------
constexpr int G_SS = 20480;
constexpr int G_AH = 0, G_AL = 5120, G_BH = 10240, G_BL = 15360;
constexpr int G_SMEM = G_SS * 3;
constexpr int G_KITERS = C_ / 32;            // 12

__device__ __forceinline__ void gemm_fill(uint32_t sb, int t,
    const __nv_bfloat16* Xh, const __nv_bfloat16* Xl,
    const __nv_bfloat16* Wh, const __nv_bfloat16* Wl,
    int bm, int bn, int k0) {
#pragma unroll
    for (int i = 0; i < 2; i++) {
        int id = t + i * 128;
        int r = id >> 2, c = id & 3;
        cp16(sb + G_AH + r * 80 + c * 16, Xh + (size_t)(bm + r) * C_ + k0 + c * 8);
        cp16(sb + G_AL + r * 80 + c * 16, Xl + (size_t)(bm + r) * C_ + k0 + c * 8);
        cp16(sb + G_BH + r * 80 + c * 16, Wh + (size_t)(bn + r) * C_ + k0 + c * 8);
        cp16(sb + G_BL + r * 80 + c * 16, Wl + (size_t)(bn + r) * C_ + k0 + c * 8);
    }
}

__global__ __launch_bounds__(128) void gemm_tc(
    const __nv_bfloat16* __restrict__ Xh, const __nv_bfloat16* __restrict__ Xl,
    const __nv_bfloat16* __restrict__ Wh, const __nv_bfloat16* __restrict__ Wl,
    const float* __restrict__ bias, float* __restrict__ out, int Nout) {
    extern __shared__ char dynsm[];
    const uint32_t smb = (uint32_t)__cvta_generic_to_shared(dynsm);

    const int bm = blockIdx.y * 64;
    const int bn = blockIdx.x * 64;
    const int t  = threadIdx.x;
    const int wid  = t >> 5;
    const int lane = t & 31;
    const int r0 = wid * 16 + (lane >> 2);
    const int qc = (lane & 3) * 2;

    float acc[8][4];
#pragma unroll
    for (int nt = 0; nt < 8; nt++)
#pragma unroll
        for (int j = 0; j < 4; j++) acc[nt][j] = 0.f;

    gemm_fill(smb, t, Xh, Xl, Wh, Wl, bm, bn, 0);
    CP_COMMIT();

    for (int ki = 0; ki < G_KITERS; ki++) {
        const int s = ki % 3;
        if (ki + 1 < G_KITERS)
            gemm_fill(smb + ((ki + 1) % 3) * G_SS, t, Xh, Xl, Wh, Wl,
                      bm, bn, (ki + 1) * 32);
        CP_COMMIT();
        CP_WAIT1();
        __syncthreads();

        const __nv_bfloat16* Ah = (const __nv_bfloat16*)(dynsm + s * G_SS + G_AH);
        const __nv_bfloat16* Al = (const __nv_bfloat16*)(dynsm + s * G_SS + G_AL);
        const __nv_bfloat16* Bh = (const __nv_bfloat16*)(dynsm + s * G_SS + G_BH);
        const __nv_bfloat16* Bl = (const __nv_bfloat16*)(dynsm + s * G_SS + G_BL);

#pragma unroll
        for (int ks = 0; ks < 2; ks++) {
            int kb = ks * 16;
            uint32_t ah[4], al[4];
            ah[0] = *(const uint32_t*)&Ah[r0 * 40 + kb + qc];
            ah[1] = *(const uint32_t*)&Ah[(r0 + 8) * 40 + kb + qc];
            ah[2] = *(const uint32_t*)&Ah[r0 * 40 + kb + qc + 8];
            ah[3] = *(const uint32_t*)&Ah[(r0 + 8) * 40 + kb + qc + 8];
            al[0] = *(const uint32_t*)&Al[r0 * 40 + kb + qc];
            al[1] = *(const uint32_t*)&Al[(r0 + 8) * 40 + kb + qc];
            al[2] = *(const uint32_t*)&Al[r0 * 40 + kb + qc + 8];
            al[3] = *(const uint32_t*)&Al[(r0 + 8) * 40 + kb + qc + 8];
#pragma unroll
            for (int nt = 0; nt < 8; nt++) {
                int kn = nt * 8 + (lane >> 2);
                uint32_t bhh[2], bll[2];
                bhh[0] = *(const uint32_t*)&Bh[kn * 40 + kb + qc];
                bhh[1] = *(const uint32_t*)&Bh[kn * 40 + kb + qc + 8];
                bll[0] = *(const uint32_t*)&Bl[kn * 40 + kb + qc];
                bll[1] = *(const uint32_t*)&Bl[kn * 40 + kb + qc + 8];
                mma16816(acc[nt], ah, bhh);
                mma16816(acc[nt], ah, bll);
                mma16816(acc[nt], al, bhh);
            }
        }
    }

#pragma unroll
    for (int nt = 0; nt < 8; nt++) {
        int n = bn + nt * 8 + qc;
        float2 bv = *(const float2*)&bias[n];
        *(float2*)&out[(size_t)(bm + r0) * Nout + n] =
            make_float2(acc[nt][0] + bv.x, acc[nt][1] + bv.y);
        *(float2*)&out[(size_t)(bm + r0 + 8) * Nout + n] =
            make_float2(acc[nt][2] + bv.x, acc[nt][3] + bv.y);
    }
}

// ---------------------------------------------------------------------------
__global__ void pbmax_kernel(const float* __restrict__ pb) {
    __shared__ float red[256];
    int h = blockIdx.x, t = threadIdx.x;
    float m = -1e30f;
    for (int i = t; i < N_; i += 256) m = fmaxf(m, pb[(size_t)h * N_ + i]);
    red[t] = m;
    __syncthreads();
    for (int s = 128; s; s >>= 1) {
        if (t < s) red[t] = fmaxf(red[t], red[t + s]);
        __syncthreads();
    }
    if (t == 0) g_pbmax[h] = red[0];
}

// ---------------------------------------------------------------------------
__global__ void qkv_epilogue_kernel(const float* __restrict__ temperature,
                                    const float* __restrict__ qe) {
    const int warp = blockIdx.x * (blockDim.x >> 5) + (threadIdx.x >> 5);
    const int lane = threadIdx.x & 31;
    if (warp >= B_ * N_ * NH_) return;
    const int h  = warp % NH_;
    const int bn = warp / NH_;
    const int n  = bn % N_;
    const int b  = bn / N_;
    const unsigned FULL = 0xFFFFFFFFu;

    float qv = g_qtmp[(size_t)bn * C_ + h * HD_ + lane];
    float ss = qv * qv;
#pragma unroll
    for (int o = 16; o; o >>= 1) ss += __shfl_xor_sync(FULL, ss, o);
    float denom = fmaxf(sqrtf(ss), 1e-12f);
    float scale = log1pf(expf(temperature[h])) * logf((float)N_);
    float qn = (qv / denom + qe[h * HD_ + lane]) * scale;
    size_t hi = ((size_t)(b * NH_ + h) * N_ + n) * HD_ + lane;
    __nv_bfloat16 qh16 = __float2bfloat16_rn(qn);
    g_qh[hi] = qh16;
    g_ql[hi] = __float2bfloat16_rn(qn - __bfloat162float(qh16));

    float ss3 = qn * qn;
#pragma unroll
    for (int o = 16; o; o >>= 1) ss3 += __shfl_xor_sync(FULL, ss3, o);
    if (lane == 0) g_qmax[(size_t)(b * NH_ + h) * N_ + n] = sqrtf(ss3);

    float kv = g_kvtmp[(size_t)bn * C2_ + h * HD_ + lane];
    float ss2 = kv * kv;
#pragma unroll
    for (int o = 16; o; o >>= 1) ss2 += __shfl_xor_sync(FULL, ss2, o);
    float kn = kv / fmaxf(sqrtf(ss2), 1e-12f);
    __nv_bfloat16 kh16 = __float2bfloat16_rn(kn);
    g_kh[hi] = kh16;
    g_kl[hi] = __float2bfloat16_rn(kn - __bfloat162float(kh16));
}

// ---------------------------------------------------------------------------
// V transpose + split: kvtmp[...,C:] (b,n,h,d) -> g_vth/g_vtl [bh][d][n]
// ---------------------------------------------------------------------------
__global__ __launch_bounds__(128) void vtrans_kernel() {
    __shared__ float Vt[32][65];
    const int bh = blockIdx.y;
    const int nb = blockIdx.x * 64;
    const int b = bh / NH_, h = bh % NH_;
    const int t = threadIdx.x;

#pragma unroll
    for (int i = 0; i < 4; i++) {
        int id = t + i * 128;
        int r = id >> 3, c4 = id & 7;
        float4 v = *(const float4*)&g_kvtmp[(size_t)(b * N_ + nb + r) * C2_ + C_ +
                                            h * HD_ + c4 * 4];
        Vt[c4 * 4 + 0][r] = v.x;
        Vt[c4 * 4 + 1][r] = v.y;
        Vt[c4 * 4 + 2][r] = v.z;
        Vt[c4 * 4 + 3][r] = v.w;
    }
    __syncthreads();
#pragma unroll
    for (int i = 0; i < 16; i++) {
        int id = t + i * 128;
        int d = id >> 6, r = id & 63;
        float v = Vt[d][r];
        float hv = bf_hi(v);
        size_t o = (size_t)(bh * HD_ + d) * N_ + nb + r;
        g_vth[o] = __float2bfloat16_rn(hv);
        g_vtl[o] = __float2bfloat16_rn(v - hv);
    }
}

// ---------------------------------------------------------------------------
// Tensor-core attention with 3-stage cp.async pipeline.
// CTA = 64 q rows of one (b,h); 4 warps x 16 rows; 64-key tiles.
// Stage layout (bytes): Kh 5120 | Kl 5120 | Vth 4608 | Vtl 4608 | pb 256
// ---------------------------------------------------------------------------
constexpr int A_SS = 19712;
constexpr int A_KH = 0, A_KL = 5120, A_VH = 10240, A_VL = 14848, A_PB = 19456;
constexpr int A_SMEM = A_SS * 3;

__device__ __forceinline__ void attn_fill(uint32_t sb, int t,
    const __nv_bfloat16* Khg, const __nv_bfloat16* Klg,
    const __nv_bfloat16* Vhg, const __nv_bfloat16* Vlg,
    const float* pbg, int kt) {
#pragma unroll
    for (int i = 0; i < 2; i++) {
        int id = t + i * 128;
        int r = id >> 2, c = id & 3;
        cp16(sb + A_KH + r * 80 + c * 16, Khg + (size_t)(kt + r) * HD_ + c * 8);
        cp16(sb + A_KL + r * 80 + c * 16, Klg + (size_t)(kt + r) * HD_ + c * 8);
        int rv = id >> 3, cv = id & 7;
        cp16(sb + A_VH + rv * 144 + cv * 16, Vhg + (size_t)rv * N_ + kt + cv * 8);
        cp16(sb + A_VL + rv * 144 + cv * 16, Vlg + (size_t)rv * N_ + kt + cv * 8);
    }
    if (t < 16) cp16(sb + A_PB + t * 16, pbg + kt + t * 4);
}

__global__ __launch_bounds__(128) void attn_mma(const float* __restrict__ pos_bias) {
    extern __shared__ char dynsm[];
    const uint32_t smb = (uint32_t)__cvta_generic_to_shared(dynsm);

    const int t     = threadIdx.x;
    const int wid   = t >> 5;
    const int lane  = t & 31;
    const int bh    = blockIdx.y;
    const int h     = bh % NH_;
    const int b     = bh / NH_;
    const int qbase = blockIdx.x * 64;
    const unsigned FULL = 0xFFFFFFFFu;

    const __nv_bfloat16* Qh_g = g_qh + (size_t)bh * N_ * HD_;
    const __nv_bfloat16* Ql_g = g_ql + (size_t)bh * N_ * HD_;
    const __nv_bfloat16* Kh_g = g_kh + (size_t)bh * N_ * HD_;
    const __nv_bfloat16* Kl_g = g_kl + (size_t)bh * N_ * HD_;
    const __nv_bfloat16* Vh_g = g_vth + (size_t)bh * HD_ * N_;
    const __nv_bfloat16* Vl_g = g_vtl + (size_t)bh * HD_ * N_;
    const float* pb_g = pos_bias + (size_t)h * N_;

    const int r0 = wid * 16 + (lane >> 2);
    const int qc = (lane & 3) * 2;

    // prologue fill (tile 0)
    attn_fill(smb, t, Kh_g, Kl_g, Vh_g, Vl_g, pb_g, 0);
    CP_COMMIT();

    // ---- Q fragments straight from gmem (persistent) ----
    uint32_t ah[2][4], al[2][4];
#pragma unroll
    for (int ks = 0; ks < 2; ks++) {
        int kb = ks * 16;
        ah[ks][0] = *(const uint32_t*)&Qh_g[(size_t)(qbase + r0) * HD_ + kb + qc];
        ah[ks][1] = *(const uint32_t*)&Qh_g[(size_t)(qbase + r0 + 8) * HD_ + kb + qc];
        ah[ks][2] = *(const uint32_t*)&Qh_g[(size_t)(qbase + r0) * HD_ + kb + qc + 8];
        ah[ks][3] = *(const uint32_t*)&Qh_g[(size_t)(qbase + r0 + 8) * HD_ + kb + qc + 8];
        al[ks][0] = *(const uint32_t*)&Ql_g[(size_t)(qbase + r0) * HD_ + kb + qc];
        al[ks][1] = *(const uint32_t*)&Ql_g[(size_t)(qbase + r0 + 8) * HD_ + kb + qc];
        al[ks][2] = *(const uint32_t*)&Ql_g[(size_t)(qbase + r0) * HD_ + kb + qc + 8];
        al[ks][3] = *(const uint32_t*)&Ql_g[(size_t)(qbase + r0 + 8) * HD_ + kb + qc + 8];
    }

    const float pmax = g_pbmax[h];
    const float mr0 = g_qmax[(size_t)bh * N_ + qbase + r0] + pmax;
    const float mr1 = g_qmax[(size_t)bh * N_ + qbase + r0 + 8] + pmax;
    float ls0 = 0.f, ls1 = 0.f;

    float oacc[4][4];
#pragma unroll
    for (int dt = 0; dt < 4; dt++)
#pragma unroll
        for (int j = 0; j < 4; j++) oacc[dt][j] = 0.f;

    for (int ki = 0; ki < N_ / 64; ki++) {
        const int s = ki % 3;
        if (ki + 1 < N_ / 64)
            attn_fill(smb + ((ki + 1) % 3) * A_SS, t, Kh_g, Kl_g, Vh_g, Vl_g,
                      pb_g, (ki + 1) * 64);
        CP_COMMIT();
        CP_WAIT1();
        __syncthreads();

        const __nv_bfloat16* Kh = (const __nv_bfloat16*)(dynsm + s * A_SS + A_KH);
        const __nv_bfloat16* Kl = (const __nv_bfloat16*)(dynsm + s * A_SS + A_KL);
        const __nv_bfloat16* Vth = (const __nv_bfloat16*)(dynsm + s * A_SS + A_VH);
        const __nv_bfloat16* Vtl = (const __nv_bfloat16*)(dynsm + s * A_SS + A_VL);
        const float* pb = (const float*)(dynsm + s * A_SS + A_PB);

        // ---- S = Q.K^T over 8 n-tiles, split 3-pass ----
        float sacc[8][4];
#pragma unroll
        for (int nt = 0; nt < 8; nt++) {
#pragma unroll
            for (int j = 0; j < 4; j++) sacc[nt][j] = 0.f;
            int kn = nt * 8 + (lane >> 2);
#pragma unroll
            for (int ks = 0; ks < 2; ks++) {
                int kb = ks * 16;
                uint32_t bhh[2], bll[2];
                bhh[0] = *(const uint32_t*)&Kh[kn * 40 + kb + qc];
                bhh[1] = *(const uint32_t*)&Kh[kn * 40 + kb + qc + 8];
                bll[0] = *(const uint32_t*)&Kl[kn * 40 + kb + qc];
                bll[1] = *(const uint32_t*)&Kl[kn * 40 + kb + qc + 8];
                mma16816(sacc[nt], ah[ks], bhh);
                mma16816(sacc[nt], ah[ks], bll);
                mma16816(sacc[nt], al[ks], bhh);
            }
        }

        // ---- softmax epilogue in registers; split P ----
        uint32_t ph2[8][2], pl2[8][2];
#pragma unroll
        for (int nt = 0; nt < 8; nt++) {
            float pc0 = pb[nt * 8 + qc], pc1 = pb[nt * 8 + qc + 1];
            float e0 = __expf(sacc[nt][0] + pc0 - mr0);
            float e1 = __expf(sacc[nt][1] + pc1 - mr0);
            float e2 = __expf(sacc[nt][2] + pc0 - mr1);
            float e3 = __expf(sacc[nt][3] + pc1 - mr1);
            ls0 += e0 + e1;
            ls1 += e2 + e3;
            float h0 = bf_hi(e0), h1 = bf_hi(e1), h2 = bf_hi(e2), h3 = bf_hi(e3);
            ph2[nt][0] = pack_bf2(h0, h1);
            ph2[nt][1] = pack_bf2(h2, h3);
            pl2[nt][0] = pack_bf2(e0 - h0, e1 - h1);
            pl2[nt][1] = pack_bf2(e2 - h2, e3 - h3);
        }

        // ---- O += P @ V ----
#pragma unroll
        for (int ks = 0; ks < 4; ks++) {
            uint32_t pah[4] = {ph2[2 * ks][0], ph2[2 * ks][1],
                               ph2[2 * ks + 1][0], ph2[2 * ks + 1][1]};
            uint32_t pal[4] = {pl2[2 * ks][0], pl2[2 * ks][1],
                               pl2[2 * ks + 1][0], pl2[2 * ks + 1][1]};
            int kb = ks * 16 + qc;
#pragma unroll
            for (int dt = 0; dt < 4; dt++) {
                int dn = dt * 8 + (lane >> 2);
                uint32_t vhh[2], vll[2];
                vhh[0] = *(const uint32_t*)&Vth[dn * 72 + kb];
                vhh[1] = *(const uint32_t*)&Vth[dn * 72 + kb + 8];
                vll[0] = *(const uint32_t*)&Vtl[dn * 72 + kb];
                vll[1] = *(const uint32_t*)&Vtl[dn * 72 + kb + 8];
                mma16816(oacc[dt], pah, vhh);
                mma16816(oacc[dt], pah, vll);
                mma16816(oacc[dt], pal, vhh);
            }
        }
    }

    // ---- reduce row sums across the quad ----
#pragma unroll
    for (int o = 1; o <= 2; o <<= 1) {
        ls0 += __shfl_xor_sync(FULL, ls0, o);
        ls1 += __shfl_xor_sync(FULL, ls1, o);
    }
    const float inv0 = 1.f / ls0, inv1 = 1.f / ls1;

    // ---- write O as split bf16 (feeds output projection) ----
    size_t o0 = (size_t)(b * N_ + qbase + r0) * C_ + h * HD_;
    size_t o1 = (size_t)(b * N_ + qbase + r0 + 8) * C_ + h * HD_;
#pragma unroll
    for (int dt = 0; dt < 4; dt++) {
        int dc = dt * 8 + qc;
        float a0 = oacc[dt][0] * inv0, a1 = oacc[dt][1] * inv0;
        float b0 = oacc[dt][2] * inv1, b1 = oacc[dt][3] * inv1;
        float h0 = bf_hi(a0), h1 = bf_hi(a1), h2 = bf_hi(b0), h3 = bf_hi(b1);
        *(uint32_t*)&g_atth[o0 + dc] = pack_bf2(h0, h1);
        *(uint32_t*)&g_attl[o0 + dc] = pack_bf2(a0 - h0, a1 - h1);
        *(uint32_t*)&g_atth[o1 + dc] = pack_bf2(h2, h3);
        *(uint32_t*)&g_attl[o1 + dc] = pack_bf2(b0 - h2, b1 - h3);
    }
}

// ---------------------------------------------------------------------------
extern "C" void kernel_launch(void* const* d_in, const int* in_sizes, int n_in,
                              void* d_out, int out_size) {
    const float* x      = (const float*)d_in[0];
    const float* q_w    = (const float*)d_in[1];
    const float* q_b    = (const float*)d_in[2];
    const float* kv_w   = (const float*)d_in[3];
    const float* kv_b   = (const float*)d_in[4];
    const float* qe     = (const float*)d_in[5];
    const float* temp   = (const float*)d_in[6];
    const float* pos_b  = (const float*)d_in[7];
    const float* proj_w = (const float*)d_in[8];
    const float* proj_b = (const float*)d_in[9];
    float* out = (float*)d_out;

    float *p_qtmp, *p_kvtmp;
    __nv_bfloat16 *p_xh, *p_xl, *p_wqh, *p_wql, *p_wkvh, *p_wkvl,
                  *p_wph, *p_wpl, *p_atth, *p_attl;
    cudaGetSymbolAddress((void**)&p_qtmp, g_qtmp);
    cudaGetSymbolAddress((void**)&p_kvtmp, g_kvtmp);
    cudaGetSymbolAddress((void**)&p_xh, g_xh);
    cudaGetSymbolAddress((void**)&p_xl, g_xl);
    cudaGetSymbolAddress((void**)&p_wqh, g_wqh);
    cudaGetSymbolAddress((void**)&p_wql, g_wql);
    cudaGetSymbolAddress((void**)&p_wkvh, g_wkvh);
    cudaGetSymbolAddress((void**)&p_wkvl, g_wkvl);
    cudaGetSymbolAddress((void**)&p_wph, g_wph);
    cudaGetSymbolAddress((void**)&p_wpl, g_wpl);
    cudaGetSymbolAddress((void**)&p_atth, g_atth);
    cudaGetSymbolAddress((void**)&p_attl, g_attl);

    static bool attr_done = false;
    if (!attr_done) {
        cudaFuncSetAttribute(gemm_tc, cudaFuncAttributeMaxDynamicSharedMemorySize,
                             G_SMEM);
        cudaFuncSetAttribute(attn_mma, cudaFuncAttributeMaxDynamicSharedMemorySize,
                             A_SMEM);
        attr_done = true;
    }

    // split conversions (x + all weights) in one launch
    conv_split_all<<<(SPL4 + 255) / 256, 256>>>(x, q_w, kv_w, proj_w);

    // projections on tensor cores (pipelined)
    gemm_tc<<<dim3(C_ / 64, M_ / 64), 128, G_SMEM>>>(p_xh, p_xl, p_wqh, p_wql,
                                                     q_b, p_qtmp, C_);
    gemm_tc<<<dim3(C2_ / 64, M_ / 64), 128, G_SMEM>>>(p_xh, p_xl, p_wkvh, p_wkvl,
                                                      kv_b, p_kvtmp, C2_);

    pbmax_kernel<<<NH_, 256>>>(pos_b);
    {
        int warps = B_ * N_ * NH_;
        qkv_epilogue_kernel<<<(warps + 7) / 8, 256>>>(temp, qe);
    }
    vtrans_kernel<<<dim3(N_ / 64, B_ * NH_), 128>>>();

    attn_mma<<<dim3(N_ / 64, B_ * NH_), 128, A_SMEM>>>(pos_b);

    gemm_tc<<<dim3(C_ / 64, M_ / 64), 128, G_SMEM>>>(p_atth, p_attl, p_wph, p_wpl,
                                                     proj_b, out, C_);
}

// round 16
// speedup vs baseline: 4.3492x; 1.0138x over previous
#include <cuda_runtime.h>
#include <cuda_bf16.h>
#include <math.h>
#include <stdint.h>

// Problem constants (fixed by the dataset)
constexpr int B_  = 2;
constexpr int N_  = 2048;
constexpr int C_  = 384;
constexpr int NH_ = 12;
constexpr int HD_ = 32;
constexpr int M_  = B_ * N_;     // 4096 tokens
constexpr int C2_ = 2 * C_;      // 768
constexpr int BHN = B_ * NH_ * N_ * HD_;

// ---------------- scratch (device globals; no allocation allowed) ----------
__device__ float g_qtmp[M_ * C_];
__device__ float g_kvtmp[M_ * C2_];
__device__ float g_qmax[B_ * NH_ * N_];
__device__ float g_pbmax[NH_];

__device__ __nv_bfloat16 g_xh[M_ * C_],  g_xl[M_ * C_];
__device__ __nv_bfloat16 g_wqh[C_ * C_], g_wql[C_ * C_];
__device__ __nv_bfloat16 g_wkvh[C2_ * C_], g_wkvl[C2_ * C_];
__device__ __nv_bfloat16 g_wph[C_ * C_], g_wpl[C_ * C_];
__device__ __nv_bfloat16 g_qh[BHN], g_ql[BHN];       // [bh][n][d]
__device__ __nv_bfloat16 g_kh[BHN], g_kl[BHN];       // [bh][n][d]
__device__ __nv_bfloat16 g_vth[BHN], g_vtl[BHN];     // [bh][d][n] (transposed)
__device__ __nv_bfloat16 g_atth[M_ * C_], g_attl[M_ * C_];

// ---------------- helpers ---------------------------------------------------
__device__ __forceinline__ void mma16816(float* d, const uint32_t* a,
                                         const uint32_t* b) {
    asm volatile(
        "mma.sync.aligned.m16n8k16.row.col.f32.bf16.bf16.f32 "
        "{%0,%1,%2,%3}, {%4,%5,%6,%7}, {%8,%9}, {%0,%1,%2,%3};"
        : "+f"(d[0]), "+f"(d[1]), "+f"(d[2]), "+f"(d[3])
        : "r"(a[0]), "r"(a[1]), "r"(a[2]), "r"(a[3]), "r"(b[0]), "r"(b[1]));
}
__device__ __forceinline__ uint32_t pack_bf2(float x, float y) {
    __nv_bfloat162 h = __floats2bfloat162_rn(x, y);
    return *(uint32_t*)&h;
}
__device__ __forceinline__ float bf_hi(float x) {
    return __bfloat162float(__float2bfloat16_rn(x));
}
__device__ __forceinline__ void cp16(uint32_t sdst, const void* gsrc) {
    asm volatile("cp.async.cg.shared.global [%0], [%1], 16;"
                 :: "r"(sdst), "l"(gsrc));
}
#define CP_COMMIT() asm volatile("cp.async.commit_group;" ::: "memory")
#define CP_WAIT1()  asm volatile("cp.async.wait_group 1;" ::: "memory")

// ---------------------------------------------------------------------------
// One launch: split x + all weights into bf16 hi/lo, AND per-head pos_bias max
// (extra 12 blocks at the tail of the grid).
// ---------------------------------------------------------------------------
constexpr int SPL1 = M_ * C_ / 4;            // x
constexpr int SPL2 = SPL1 + C_ * C_ / 4;     // q_w
constexpr int SPL3 = SPL2 + C2_ * C_ / 4;    // kv_w
constexpr int SPL4 = SPL3 + C_ * C_ / 4;     // proj_w   (= 540672, 2112 blocks)
constexpr int SPLIT_BLOCKS = SPL4 / 256;

__global__ void prep_all(const float* __restrict__ x,
                         const float* __restrict__ qw,
                         const float* __restrict__ kvw,
                         const float* __restrict__ pw,
                         const float* __restrict__ pb) {
    if (blockIdx.x >= SPLIT_BLOCKS) {
        __shared__ float red[256];
        int h = blockIdx.x - SPLIT_BLOCKS, t = threadIdx.x;
        float m = -1e30f;
        for (int i = t; i < N_; i += 256) m = fmaxf(m, pb[(size_t)h * N_ + i]);
        red[t] = m;
        __syncthreads();
        for (int s = 128; s; s >>= 1) {
            if (t < s) red[t] = fmaxf(red[t], red[t + s]);
            __syncthreads();
        }
        if (t == 0) g_pbmax[h] = red[0];
        return;
    }
    int i = blockIdx.x * 256 + threadIdx.x;
    const float* src;
    __nv_bfloat16 *hi, *lo;
    int j;
    if (i < SPL1)      { src = x;   hi = g_xh;  lo = g_xl;  j = i; }
    else if (i < SPL2) { src = qw;  hi = g_wqh; lo = g_wql; j = i - SPL1; }
    else if (i < SPL3) { src = kvw; hi = g_wkvh; lo = g_wkvl; j = i - SPL2; }
    else               { src = pw;  hi = g_wph; lo = g_wpl; j = i - SPL3; }
    float4 v = ((const float4*)src)[j];
    float hx = bf_hi(v.x), hy = bf_hi(v.y), hz = bf_hi(v.z), hw = bf_hi(v.w);
    ((uint2*)hi)[j] = make_uint2(pack_bf2(hx, hy), pack_bf2(hz, hw));
    ((uint2*)lo)[j] = make_uint2(pack_bf2(v.x - hx, v.y - hy),
                                 pack_bf2(v.z - hz, v.w - hw));
}

// ---------------------------------------------------------------------------
// Tensor-core projection GEMM with 3-stage cp.async pipeline (bf16 split).
// ---------------------------------------------------------------------------
constexpr int G_SS = 20480;
constexpr int G_AH = 0, G_AL = 5120, G_BH = 10240, G_BL = 15360;
constexpr int G_SMEM = G_SS * 3;
constexpr int G_KITERS = C_ / 32;            // 12

__device__ __forceinline__ void gemm_fill(uint32_t sb, int t,
    const __nv_bfloat16* Xh, const __nv_bfloat16* Xl,
    const __nv_bfloat16* Wh, const __nv_bfloat16* Wl,
    int bm, int bn, int k0) {
#pragma unroll
    for (int i = 0; i < 2; i++) {
        int id = t + i * 128;
        int r = id >> 2, c = id & 3;
        cp16(sb + G_AH + r * 80 + c * 16, Xh + (size_t)(bm + r) * C_ + k0 + c * 8);
        cp16(sb + G_AL + r * 80 + c * 16, Xl + (size_t)(bm + r) * C_ + k0 + c * 8);
        cp16(sb + G_BH + r * 80 + c * 16, Wh + (size_t)(bn + r) * C_ + k0 + c * 8);
        cp16(sb + G_BL + r * 80 + c * 16, Wl + (size_t)(bn + r) * C_ + k0 + c * 8);
    }
}

__global__ __launch_bounds__(128) void gemm_tc(
    const __nv_bfloat16* __restrict__ Xh, const __nv_bfloat16* __restrict__ Xl,
    const __nv_bfloat16* __restrict__ Wh, const __nv_bfloat16* __restrict__ Wl,
    const float* __restrict__ bias, float* __restrict__ out, int Nout) {
    extern __shared__ char dynsm[];
    const uint32_t smb = (uint32_t)__cvta_generic_to_shared(dynsm);

    const int bm = blockIdx.y * 64;
    const int bn = blockIdx.x * 64;
    const int t  = threadIdx.x;
    const int wid  = t >> 5;
    const int lane = t & 31;
    const int r0 = wid * 16 + (lane >> 2);
    const int qc = (lane & 3) * 2;

    float acc[8][4];
#pragma unroll
    for (int nt = 0; nt < 8; nt++)
#pragma unroll
        for (int j = 0; j < 4; j++) acc[nt][j] = 0.f;

    gemm_fill(smb, t, Xh, Xl, Wh, Wl, bm, bn, 0);
    CP_COMMIT();

    for (int ki = 0; ki < G_KITERS; ki++) {
        const int s = ki % 3;
        if (ki + 1 < G_KITERS)
            gemm_fill(smb + ((ki + 1) % 3) * G_SS, t, Xh, Xl, Wh, Wl,
                      bm, bn, (ki + 1) * 32);
        CP_COMMIT();
        CP_WAIT1();
        __syncthreads();

        const __nv_bfloat16* Ah = (const __nv_bfloat16*)(dynsm + s * G_SS + G_AH);
        const __nv_bfloat16* Al = (const __nv_bfloat16*)(dynsm + s * G_SS + G_AL);
        const __nv_bfloat16* Bh = (const __nv_bfloat16*)(dynsm + s * G_SS + G_BH);
        const __nv_bfloat16* Bl = (const __nv_bfloat16*)(dynsm + s * G_SS + G_BL);

#pragma unroll
        for (int ks = 0; ks < 2; ks++) {
            int kb = ks * 16;
            uint32_t ah[4], al[4];
            ah[0] = *(const uint32_t*)&Ah[r0 * 40 + kb + qc];
            ah[1] = *(const uint32_t*)&Ah[(r0 + 8) * 40 + kb + qc];
            ah[2] = *(const uint32_t*)&Ah[r0 * 40 + kb + qc + 8];
            ah[3] = *(const uint32_t*)&Ah[(r0 + 8) * 40 + kb + qc + 8];
            al[0] = *(const uint32_t*)&Al[r0 * 40 + kb + qc];
            al[1] = *(const uint32_t*)&Al[(r0 + 8) * 40 + kb + qc];
            al[2] = *(const uint32_t*)&Al[r0 * 40 + kb + qc + 8];
            al[3] = *(const uint32_t*)&Al[(r0 + 8) * 40 + kb + qc + 8];
#pragma unroll
            for (int nt = 0; nt < 8; nt++) {
                int kn = nt * 8 + (lane >> 2);
                uint32_t bhh[2], bll[2];
                bhh[0] = *(const uint32_t*)&Bh[kn * 40 + kb + qc];
                bhh[1] = *(const uint32_t*)&Bh[kn * 40 + kb + qc + 8];
                bll[0] = *(const uint32_t*)&Bl[kn * 40 + kb + qc];
                bll[1] = *(const uint32_t*)&Bl[kn * 40 + kb + qc + 8];
                mma16816(acc[nt], ah, bhh);
                mma16816(acc[nt], ah, bll);
                mma16816(acc[nt], al, bhh);
            }
        }
    }

#pragma unroll
    for (int nt = 0; nt < 8; nt++) {
        int n = bn + nt * 8 + qc;
        float2 bv = *(const float2*)&bias[n];
        *(float2*)&out[(size_t)(bm + r0) * Nout + n] =
            make_float2(acc[nt][0] + bv.x, acc[nt][1] + bv.y);
        *(float2*)&out[(size_t)(bm + r0 + 8) * Nout + n] =
            make_float2(acc[nt][2] + bv.x, acc[nt][3] + bv.y);
    }
}

// ---------------------------------------------------------------------------
// Merged Q/K epilogue + V transpose. CTA = (bh, 64-token chunk), 128 threads.
// Threads 0-63: Q rows (in-thread L2 norm, embed, scale, bf16 split, qmax).
// Threads 64-127: K rows (in-thread L2 norm, bf16 split).
// All threads: V transpose+split via smem.
// ---------------------------------------------------------------------------
__global__ __launch_bounds__(128) void qkv_prep_kernel(
    const float* __restrict__ temperature, const float* __restrict__ qe) {
    __shared__ float Vt[32][65];
    __shared__ float qes[HD_];
    const int bh = blockIdx.y;
    const int nb = blockIdx.x * 64;
    const int b = bh / NH_, h = bh % NH_;
    const int t = threadIdx.x;

    if (t < HD_) qes[t] = qe[h * HD_ + t];
    __syncthreads();

    {
        const int tok = nb + (t & 63);
        float v[32];
        if (t < 64) {
            const float4* row = (const float4*)&g_qtmp[(size_t)(b * N_ + tok) * C_ + h * HD_];
#pragma unroll
            for (int c = 0; c < 8; c++) {
                float4 f = row[c];
                v[c * 4] = f.x; v[c * 4 + 1] = f.y; v[c * 4 + 2] = f.z; v[c * 4 + 3] = f.w;
            }
            float ss = 0.f;
#pragma unroll
            for (int d = 0; d < 32; d++) ss += v[d] * v[d];
            float inv = 1.f / fmaxf(sqrtf(ss), 1e-12f);
            float scale = log1pf(expf(temperature[h])) * logf((float)N_);
            float ss3 = 0.f;
#pragma unroll
            for (int d = 0; d < 32; d++) {
                v[d] = (v[d] * inv + qes[d]) * scale;
                ss3 += v[d] * v[d];
            }
            g_qmax[(size_t)bh * N_ + tok] = sqrtf(ss3);
            size_t o = ((size_t)bh * N_ + tok) * HD_;
#pragma unroll
            for (int c = 0; c < 8; c++) {
                float a0 = v[c * 4], a1 = v[c * 4 + 1], a2 = v[c * 4 + 2], a3 = v[c * 4 + 3];
                float h0 = bf_hi(a0), h1 = bf_hi(a1), h2 = bf_hi(a2), h3 = bf_hi(a3);
                ((uint2*)&g_qh[o])[c] = make_uint2(pack_bf2(h0, h1), pack_bf2(h2, h3));
                ((uint2*)&g_ql[o])[c] = make_uint2(pack_bf2(a0 - h0, a1 - h1),
                                                   pack_bf2(a2 - h2, a3 - h3));
            }
        } else {
            const float4* row = (const float4*)&g_kvtmp[(size_t)(b * N_ + tok) * C2_ + h * HD_];
#pragma unroll
            for (int c = 0; c < 8; c++) {
                float4 f = row[c];
                v[c * 4] = f.x; v[c * 4 + 1] = f.y; v[c * 4 + 2] = f.z; v[c * 4 + 3] = f.w;
            }
            float ss = 0.f;
#pragma unroll
            for (int d = 0; d < 32; d++) ss += v[d] * v[d];
            float inv = 1.f / fmaxf(sqrtf(ss), 1e-12f);
            size_t o = ((size_t)bh * N_ + tok) * HD_;
#pragma unroll
            for (int c = 0; c < 8; c++) {
                float a0 = v[c * 4] * inv, a1 = v[c * 4 + 1] * inv;
                float a2 = v[c * 4 + 2] * inv, a3 = v[c * 4 + 3] * inv;
                float h0 = bf_hi(a0), h1 = bf_hi(a1), h2 = bf_hi(a2), h3 = bf_hi(a3);
                ((uint2*)&g_kh[o])[c] = make_uint2(pack_bf2(h0, h1), pack_bf2(h2, h3));
                ((uint2*)&g_kl[o])[c] = make_uint2(pack_bf2(a0 - h0, a1 - h1),
                                                   pack_bf2(a2 - h2, a3 - h3));
            }
        }
    }

    // ---- V transpose + split ----
#pragma unroll
    for (int i = 0; i < 4; i++) {
        int id = t + i * 128;
        int r = id >> 3, c4 = id & 7;
        float4 v = *(const float4*)&g_kvtmp[(size_t)(b * N_ + nb + r) * C2_ + C_ +
                                            h * HD_ + c4 * 4];
        Vt[c4 * 4 + 0][r] = v.x;
        Vt[c4 * 4 + 1][r] = v.y;
        Vt[c4 * 4 + 2][r] = v.z;
        Vt[c4 * 4 + 3][r] = v.w;
    }
    __syncthreads();
#pragma unroll
    for (int i = 0; i < 16; i++) {
        int id = t + i * 128;
        int d = id >> 6, r = id & 63;
        float v = Vt[d][r];
        float hv = bf_hi(v);
        size_t o = (size_t)(bh * HD_ + d) * N_ + nb + r;
        g_vth[o] = __float2bfloat16_rn(hv);
        g_vtl[o] = __float2bfloat16_rn(v - hv);
    }
}

// ---------------------------------------------------------------------------
// Tensor-core attention with 3-stage cp.async pipeline (bf16 split, 3-pass
// S and PV). CTA = 64 q rows of one (b,h); 64-key tiles.
// ---------------------------------------------------------------------------
constexpr int A_SS = 19712;
constexpr int A_KH = 0, A_KL = 5120, A_VH = 10240, A_VL = 14848, A_PB = 19456;
constexpr int A_SMEM = A_SS * 3;

__device__ __forceinline__ void attn_fill(uint32_t sb, int t,
    const __nv_bfloat16* Khg, const __nv_bfloat16* Klg,
    const __nv_bfloat16* Vhg, const __nv_bfloat16* Vlg,
    const float* pbg, int kt) {
#pragma unroll
    for (int i = 0; i < 2; i++) {
        int id = t + i * 128;
        int r = id >> 2, c = id & 3;
        cp16(sb + A_KH + r * 80 + c * 16, Khg + (size_t)(kt + r) * HD_ + c * 8);
        cp16(sb + A_KL + r * 80 + c * 16, Klg + (size_t)(kt + r) * HD_ + c * 8);
        int rv = id >> 3, cv = id & 7;
        cp16(sb + A_VH + rv * 144 + cv * 16, Vhg + (size_t)rv * N_ + kt + cv * 8);
        cp16(sb + A_VL + rv * 144 + cv * 16, Vlg + (size_t)rv * N_ + kt + cv * 8);
    }
    if (t < 16) cp16(sb + A_PB + t * 16, pbg + kt + t * 4);
}

__global__ __launch_bounds__(128) void attn_mma(const float* __restrict__ pos_bias) {
    extern __shared__ char dynsm[];
    const uint32_t smb = (uint32_t)__cvta_generic_to_shared(dynsm);

    const int t     = threadIdx.x;
    const int wid   = t >> 5;
    const int lane  = t & 31;
    const int bh    = blockIdx.y;
    const int h     = bh % NH_;
    const int b     = bh / NH_;
    const int qbase = blockIdx.x * 64;
    const unsigned FULL = 0xFFFFFFFFu;

    const __nv_bfloat16* Qh_g = g_qh + (size_t)bh * N_ * HD_;
    const __nv_bfloat16* Ql_g = g_ql + (size_t)bh * N_ * HD_;
    const __nv_bfloat16* Kh_g = g_kh + (size_t)bh * N_ * HD_;
    const __nv_bfloat16* Kl_g = g_kl + (size_t)bh * N_ * HD_;
    const __nv_bfloat16* Vh_g = g_vth + (size_t)bh * HD_ * N_;
    const __nv_bfloat16* Vl_g = g_vtl + (size_t)bh * HD_ * N_;
    const float* pb_g = pos_bias + (size_t)h * N_;

    const int r0 = wid * 16 + (lane >> 2);
    const int qc = (lane & 3) * 2;

    attn_fill(smb, t, Kh_g, Kl_g, Vh_g, Vl_g, pb_g, 0);
    CP_COMMIT();

    uint32_t ah[2][4], al[2][4];
#pragma unroll
    for (int ks = 0; ks < 2; ks++) {
        int kb = ks * 16;
        ah[ks][0] = *(const uint32_t*)&Qh_g[(size_t)(qbase + r0) * HD_ + kb + qc];
        ah[ks][1] = *(const uint32_t*)&Qh_g[(size_t)(qbase + r0 + 8) * HD_ + kb + qc];
        ah[ks][2] = *(const uint32_t*)&Qh_g[(size_t)(qbase + r0) * HD_ + kb + qc + 8];
        ah[ks][3] = *(const uint32_t*)&Qh_g[(size_t)(qbase + r0 + 8) * HD_ + kb + qc + 8];
        al[ks][0] = *(const uint32_t*)&Ql_g[(size_t)(qbase + r0) * HD_ + kb + qc];
        al[ks][1] = *(const uint32_t*)&Ql_g[(size_t)(qbase + r0 + 8) * HD_ + kb + qc];
        al[ks][2] = *(const uint32_t*)&Ql_g[(size_t)(qbase + r0) * HD_ + kb + qc + 8];
        al[ks][3] = *(const uint32_t*)&Ql_g[(size_t)(qbase + r0 + 8) * HD_ + kb + qc + 8];
    }

    const float pmax = g_pbmax[h];
    const float mr0 = g_qmax[(size_t)bh * N_ + qbase + r0] + pmax;
    const float mr1 = g_qmax[(size_t)bh * N_ + qbase + r0 + 8] + pmax;
    float ls0 = 0.f, ls1 = 0.f;

    float oacc[4][4];
#pragma unroll
    for (int dt = 0; dt < 4; dt++)
#pragma unroll
        for (int j = 0; j < 4; j++) oacc[dt][j] = 0.f;

    for (int ki = 0; ki < N_ / 64; ki++) {
        const int s = ki % 3;
        if (ki + 1 < N_ / 64)
            attn_fill(smb + ((ki + 1) % 3) * A_SS, t, Kh_g, Kl_g, Vh_g, Vl_g,
                      pb_g, (ki + 1) * 64);
        CP_COMMIT();
        CP_WAIT1();
        __syncthreads();

        const __nv_bfloat16* Kh = (const __nv_bfloat16*)(dynsm + s * A_SS + A_KH);
        const __nv_bfloat16* Kl = (const __nv_bfloat16*)(dynsm + s * A_SS + A_KL);
        const __nv_bfloat16* Vth = (const __nv_bfloat16*)(dynsm + s * A_SS + A_VH);
        const __nv_bfloat16* Vtl = (const __nv_bfloat16*)(dynsm + s * A_SS + A_VL);
        const float* pb = (const float*)(dynsm + s * A_SS + A_PB);

        // ---- S = Q.K^T over 8 n-tiles, split 3-pass ----
        float sacc[8][4];
#pragma unroll
        for (int nt = 0; nt < 8; nt++) {
#pragma unroll
            for (int j = 0; j < 4; j++) sacc[nt][j] = 0.f;
            int kn = nt * 8 + (lane >> 2);
#pragma unroll
            for (int ks = 0; ks < 2; ks++) {
                int kb = ks * 16;
                uint32_t bhh[2], bll[2];
                bhh[0] = *(const uint32_t*)&Kh[kn * 40 + kb + qc];
                bhh[1] = *(const uint32_t*)&Kh[kn * 40 + kb + qc + 8];
                bll[0] = *(const uint32_t*)&Kl[kn * 40 + kb + qc];
                bll[1] = *(const uint32_t*)&Kl[kn * 40 + kb + qc + 8];
                mma16816(sacc[nt], ah[ks], bhh);
                mma16816(sacc[nt], ah[ks], bll);
                mma16816(sacc[nt], al[ks], bhh);
            }
        }

        // ---- softmax epilogue in registers; split P to bf16 hi/lo ----
        uint32_t ph2[8][2], pl2[8][2];
#pragma unroll
        for (int nt = 0; nt < 8; nt++) {
            float pc0 = pb[nt * 8 + qc], pc1 = pb[nt * 8 + qc + 1];
            float e0 = __expf(sacc[nt][0] + pc0 - mr0);
            float e1 = __expf(sacc[nt][1] + pc1 - mr0);
            float e2 = __expf(sacc[nt][2] + pc0 - mr1);
            float e3 = __expf(sacc[nt][3] + pc1 - mr1);
            ls0 += e0 + e1;
            ls1 += e2 + e3;
            float h0 = bf_hi(e0), h1 = bf_hi(e1), h2 = bf_hi(e2), h3 = bf_hi(e3);
            ph2[nt][0] = pack_bf2(h0, h1);
            ph2[nt][1] = pack_bf2(h2, h3);
            pl2[nt][0] = pack_bf2(e0 - h0, e1 - h1);
            pl2[nt][1] = pack_bf2(e2 - h2, e3 - h3);
        }

        // ---- O += P @ V (3 passes) ----
#pragma unroll
        for (int ks = 0; ks < 4; ks++) {
            uint32_t pah[4] = {ph2[2 * ks][0], ph2[2 * ks][1],
                               ph2[2 * ks + 1][0], ph2[2 * ks + 1][1]};
            uint32_t pal[4] = {pl2[2 * ks][0], pl2[2 * ks][1],
                               pl2[2 * ks + 1][0], pl2[2 * ks + 1][1]};
            int kb = ks * 16 + qc;
#pragma unroll
            for (int dt = 0; dt < 4; dt++) {
                int dn = dt * 8 + (lane >> 2);
                uint32_t vhh[2], vll[2];
                vhh[0] = *(const uint32_t*)&Vth[dn * 72 + kb];
                vhh[1] = *(const uint32_t*)&Vth[dn * 72 + kb + 8];
                vll[0] = *(const uint32_t*)&Vtl[dn * 72 + kb];
                vll[1] = *(const uint32_t*)&Vtl[dn * 72 + kb + 8];
                mma16816(oacc[dt], pah, vhh);
                mma16816(oacc[dt], pah, vll);
                mma16816(oacc[dt], pal, vhh);
            }
        }
    }

    // ---- reduce row sums across the quad ----
#pragma unroll
    for (int o = 1; o <= 2; o <<= 1) {
        ls0 += __shfl_xor_sync(FULL, ls0, o);
        ls1 += __shfl_xor_sync(FULL, ls1, o);
    }
    const float inv0 = 1.f / ls0, inv1 = 1.f / ls1;

    // ---- write O as split bf16 (feeds output projection) ----
    size_t o0 = (size_t)(b * N_ + qbase + r0) * C_ + h * HD_;
    size_t o1 = (size_t)(b * N_ + qbase + r0 + 8) * C_ + h * HD_;
#pragma unroll
    for (int dt = 0; dt < 4; dt++) {
        int dc = dt * 8 + qc;
        float a0 = oacc[dt][0] * inv0, a1 = oacc[dt][1] * inv0;
        float b0 = oacc[dt][2] * inv1, b1 = oacc[dt][3] * inv1;
        float h0 = bf_hi(a0), h1 = bf_hi(a1), h2 = bf_hi(b0), h3 = bf_hi(b1);
        *(uint32_t*)&g_atth[o0 + dc] = pack_bf2(h0, h1);
        *(uint32_t*)&g_attl[o0 + dc] = pack_bf2(a0 - h0, a1 - h1);
        *(uint32_t*)&g_atth[o1 + dc] = pack_bf2(h2, h3);
        *(uint32_t*)&g_attl[o1 + dc] = pack_bf2(b0 - h2, b1 - h3);
    }
}

// ---------------------------------------------------------------------------
extern "C" void kernel_launch(void* const* d_in, const int* in_sizes, int n_in,
                              void* d_out, int out_size) {
    const float* x      = (const float*)d_in[0];
    const float* q_w    = (const float*)d_in[1];
    const float* q_b    = (const float*)d_in[2];
    const float* kv_w   = (const float*)d_in[3];
    const float* kv_b   = (const float*)d_in[4];
    const float* qe     = (const float*)d_in[5];
    const float* temp   = (const float*)d_in[6];
    const float* pos_b  = (const float*)d_in[7];
    const float* proj_w = (const float*)d_in[8];
    const float* proj_b = (const float*)d_in[9];
    float* out = (float*)d_out;

    float *p_qtmp, *p_kvtmp;
    __nv_bfloat16 *p_xh, *p_xl, *p_wqh, *p_wql, *p_wkvh, *p_wkvl,
                  *p_wph, *p_wpl, *p_atth, *p_attl;
    cudaGetSymbolAddress((void**)&p_qtmp, g_qtmp);
    cudaGetSymbolAddress((void**)&p_kvtmp, g_kvtmp);
    cudaGetSymbolAddress((void**)&p_xh, g_xh);
    cudaGetSymbolAddress((void**)&p_xl, g_xl);
    cudaGetSymbolAddress((void**)&p_wqh, g_wqh);
    cudaGetSymbolAddress((void**)&p_wql, g_wql);
    cudaGetSymbolAddress((void**)&p_wkvh, g_wkvh);
    cudaGetSymbolAddress((void**)&p_wkvl, g_wkvl);
    cudaGetSymbolAddress((void**)&p_wph, g_wph);
    cudaGetSymbolAddress((void**)&p_wpl, g_wpl);
    cudaGetSymbolAddress((void**)&p_atth, g_atth);
    cudaGetSymbolAddress((void**)&p_attl, g_attl);

    static bool attr_done = false;
    if (!attr_done) {
        cudaFuncSetAttribute(gemm_tc, cudaFuncAttributeMaxDynamicSharedMemorySize,
                             G_SMEM);
        cudaFuncSetAttribute(attn_mma, cudaFuncAttributeMaxDynamicSharedMemorySize,
                             A_SMEM);
        attr_done = true;
    }

    // splits + pos_bias max in one launch
    prep_all<<<SPLIT_BLOCKS + NH_, 256>>>(x, q_w, kv_w, proj_w, pos_b);

    // projections on tensor cores (pipelined)
    gemm_tc<<<dim3(C_ / 64, M_ / 64), 128, G_SMEM>>>(p_xh, p_xl, p_wqh, p_wql,
                                                     q_b, p_qtmp, C_);
    gemm_tc<<<dim3(C2_ / 64, M_ / 64), 128, G_SMEM>>>(p_xh, p_xl, p_wkvh, p_wkvl,
                                                      kv_b, p_kvtmp, C2_);

    // merged Q/K epilogue + V transpose
    qkv_prep_kernel<<<dim3(N_ / 64, B_ * NH_), 128>>>(temp, qe);

    attn_mma<<<dim3(N_ / 64, B_ * NH_), 128, A_SMEM>>>(pos_b);

    gemm_tc<<<dim3(C_ / 64, M_ / 64), 128, G_SMEM>>>(p_atth, p_attl, p_wph, p_wpl,
                                                     proj_b, out, C_);
}